// round 1
// baseline (speedup 1.0000x reference)
#include <cuda_runtime.h>
#include <cuda_bf16.h>
#include <math.h>

// Problem dims (fixed by the reference)
constexpr int Bn  = 256;            // batch
constexpr int Sn  = 20;
constexpr int En  = 512;
constexpr int Hn  = 512;
constexpr int Vn  = 32000;
constexpr int XW  = Sn * En + 2 * En;   // 11264  (enc_flat + word + speaker)
constexpr int XHW = XW + Hn;            // 11776  (x concat h0, for fused GEMM A)
constexpr int G4  = 4 * Hn;             // 2048

// Scratch (static device globals; no allocation allowed)
__device__ __align__(16) float g_xh[Bn * XHW];     // [x | h0]
__device__ __align__(16) float g_z[Bn * G4];       // gate pre-activations
__device__ __align__(16) float g_h[Bn * Hn];
__device__ __align__(16) float g_c[Bn * Hn];
__device__ __align__(16) float g_wsum[Hn * G4];    // W_l + U_l for layers 2..4

// ---------------------------------------------------------------------------
// Build [x | h0]: x = concat(enc_flat, word_embedding, persona_emb[speaker])
// ---------------------------------------------------------------------------
__global__ void build_xh_kernel(const float* __restrict__ enc,
                                const float* __restrict__ word,
                                const float* __restrict__ persona,
                                const int*   __restrict__ speaker,
                                const float* __restrict__ h0)
{
    int idx = blockIdx.x * blockDim.x + threadIdx.x;
    if (idx >= Bn * XHW) return;
    int b = idx / XHW;
    int col = idx - b * XHW;
    float v;
    if (col < Sn * En) {
        v = enc[b * (Sn * En) + col];
    } else if (col < Sn * En + En) {
        v = word[b * En + (col - Sn * En)];
    } else if (col < XW) {
        v = persona[speaker[b] * En + (col - Sn * En - En)];
    } else {
        v = h0[b * Hn + (col - XW)];
    }
    g_xh[idx] = v;
}

// ---------------------------------------------------------------------------
// Generic fp32 SGEMM: C[M x N] (+)= A[M x K] @ Bw[K x N] (+ bias)
// 64x64 block tile, BK=16, 4x4 per thread, 256 threads.
// All dims here are multiples of the tile sizes (M=256; N in {2048,32000};
// K in {512, 11264}); all leading dims are multiples of 4.
// ---------------------------------------------------------------------------
__global__ void sgemm64_kernel(const float* __restrict__ A, int lda,
                               const float* __restrict__ Bw, int ldw,
                               const float* __restrict__ bias,
                               float* __restrict__ C, int ldc,
                               int K, int accFlag)
{
    __shared__ __align__(16) float As[16][65];   // [k][m], padded (scalar reads)
    __shared__ __align__(16) float Bs[16][64];   // [k][n]

    const int tid = threadIdx.x;
    const int m0 = blockIdx.y * 64;
    const int n0 = blockIdx.x * 64;
    const int ty = tid >> 4;          // 0..15
    const int tx = tid & 15;          // 0..15
    const int arow = tid >> 2;        // 0..63
    const int acol = (tid & 3) << 2;  // 0,4,8,12
    const int brow = tid >> 4;        // 0..15
    const int bcol = (tid & 15) << 2; // 0..60

    const float* Aptr = A + (size_t)(m0 + arow) * lda + acol;
    const float* Bptr = Bw + (size_t)brow * ldw + n0 + bcol;

    float acc00 = 0.f, acc01 = 0.f, acc02 = 0.f, acc03 = 0.f;
    float acc10 = 0.f, acc11 = 0.f, acc12 = 0.f, acc13 = 0.f;
    float acc20 = 0.f, acc21 = 0.f, acc22 = 0.f, acc23 = 0.f;
    float acc30 = 0.f, acc31 = 0.f, acc32 = 0.f, acc33 = 0.f;

    for (int k0 = 0; k0 < K; k0 += 16) {
        float4 av = *(const float4*)Aptr;  Aptr += 16;
        As[acol + 0][arow] = av.x;
        As[acol + 1][arow] = av.y;
        As[acol + 2][arow] = av.z;
        As[acol + 3][arow] = av.w;
        float4 bv = *(const float4*)Bptr;  Bptr += (size_t)16 * ldw;
        *(float4*)(&Bs[brow][bcol]) = bv;
        __syncthreads();

        #pragma unroll
        for (int k = 0; k < 16; k++) {
            const float a0 = As[k][(ty << 2) + 0];
            const float a1 = As[k][(ty << 2) + 1];
            const float a2 = As[k][(ty << 2) + 2];
            const float a3 = As[k][(ty << 2) + 3];
            const float4 bb = *(const float4*)(&Bs[k][tx << 2]);
            acc00 += a0 * bb.x; acc01 += a0 * bb.y; acc02 += a0 * bb.z; acc03 += a0 * bb.w;
            acc10 += a1 * bb.x; acc11 += a1 * bb.y; acc12 += a1 * bb.z; acc13 += a1 * bb.w;
            acc20 += a2 * bb.x; acc21 += a2 * bb.y; acc22 += a2 * bb.z; acc23 += a2 * bb.w;
            acc30 += a3 * bb.x; acc31 += a3 * bb.y; acc32 += a3 * bb.z; acc33 += a3 * bb.w;
        }
        __syncthreads();
    }

    float4 bias4 = make_float4(0.f, 0.f, 0.f, 0.f);
    if (bias) bias4 = *(const float4*)(bias + n0 + (tx << 2));

    float r0[4] = {acc00, acc01, acc02, acc03};
    float r1[4] = {acc10, acc11, acc12, acc13};
    float r2[4] = {acc20, acc21, acc22, acc23};
    float r3[4] = {acc30, acc31, acc32, acc33};
    float* rows[4] = {r0, r1, r2, r3};

    #pragma unroll
    for (int i = 0; i < 4; i++) {
        float* cp = C + (size_t)(m0 + (ty << 2) + i) * ldc + n0 + (tx << 2);
        float4 out;
        out.x = rows[i][0] + bias4.x;
        out.y = rows[i][1] + bias4.y;
        out.z = rows[i][2] + bias4.z;
        out.w = rows[i][3] + bias4.w;
        if (accFlag) {
            float4 old = *(const float4*)cp;
            out.x += old.x; out.y += old.y; out.z += old.z; out.w += old.w;
        }
        *(float4*)cp = out;
    }
}

// ---------------------------------------------------------------------------
// LSTM gates: z (B x 4H) gate order [i,f,g,o]; activation relu,
// recurrent_activation sigmoid. c' = sig(f)*c + sig(i)*relu(g);
// h' = sig(o)*relu(c').  In-place safe (elementwise per idx).
// ---------------------------------------------------------------------------
__device__ __forceinline__ float sigf(float x) { return 1.0f / (1.0f + expf(-x)); }

__global__ void lstm_gates_kernel(const float* __restrict__ z,
                                  const float* __restrict__ c_in,
                                  float* __restrict__ h_out,
                                  float* __restrict__ c_out)
{
    int idx = blockIdx.x * blockDim.x + threadIdx.x;
    if (idx >= Bn * Hn) return;
    int b = idx / Hn;
    int j = idx - b * Hn;
    const float* zr = z + (size_t)b * G4;
    float gi = sigf(zr[j]);
    float gf = sigf(zr[Hn + j]);
    float gg = fmaxf(zr[2 * Hn + j], 0.f);
    float go = sigf(zr[3 * Hn + j]);
    float c = gf * c_in[idx] + gi * gg;
    c_out[idx] = c;
    h_out[idx] = go * fmaxf(c, 0.f);
}

// wsum = W + U  (since layers 2..4 use x == h)
__global__ void add_w_kernel(const float* __restrict__ W, const float* __restrict__ U)
{
    int idx = blockIdx.x * blockDim.x + threadIdx.x;
    if (idx < Hn * G4) g_wsum[idx] = W[idx] + U[idx];
}

// ---------------------------------------------------------------------------
// In-place row softmax over V=32000, one block of 256 threads per row.
// ---------------------------------------------------------------------------
__global__ void softmax_rows_kernel(float* __restrict__ logits)
{
    __shared__ float red[8];
    __shared__ float bcast;
    const int b = blockIdx.x;
    float* row = logits + (size_t)b * Vn;
    const int tid = threadIdx.x;

    float m = -1e30f;
    for (int j = tid; j < Vn; j += 256) m = fmaxf(m, row[j]);
    #pragma unroll
    for (int o = 16; o; o >>= 1) m = fmaxf(m, __shfl_xor_sync(0xffffffffu, m, o));
    if ((tid & 31) == 0) red[tid >> 5] = m;
    __syncthreads();
    if (tid == 0) {
        float mm = red[0];
        #pragma unroll
        for (int i = 1; i < 8; i++) mm = fmaxf(mm, red[i]);
        bcast = mm;
    }
    __syncthreads();
    m = bcast;
    __syncthreads();

    float s = 0.f;
    for (int j = tid; j < Vn; j += 256) s += expf(row[j] - m);
    #pragma unroll
    for (int o = 16; o; o >>= 1) s += __shfl_xor_sync(0xffffffffu, s, o);
    if ((tid & 31) == 0) red[tid >> 5] = s;
    __syncthreads();
    if (tid == 0) {
        float ss = 0.f;
        #pragma unroll
        for (int i = 0; i < 8; i++) ss += red[i];
        bcast = ss;
    }
    __syncthreads();
    const float inv = 1.0f / bcast;
    for (int j = tid; j < Vn; j += 256) row[j] = expf(row[j] - m) * inv;
}

// Copy final (h4, c4) into output tail
__global__ void copy_states_kernel(float* __restrict__ out_h, float* __restrict__ out_c)
{
    int idx = blockIdx.x * blockDim.x + threadIdx.x;
    if (idx < Bn * Hn) {
        out_h[idx] = g_h[idx];
        out_c[idx] = g_c[idx];
    }
}

// ---------------------------------------------------------------------------
// Launch
// ---------------------------------------------------------------------------
extern "C" void kernel_launch(void* const* d_in, const int* in_sizes, int n_in,
                              void* d_out, int out_size)
{
    const float* enc     = (const float*)d_in[0];
    const float* word    = (const float*)d_in[1];
    const float* h0      = (const float*)d_in[2];
    const float* c0      = (const float*)d_in[3];
    const int*   speaker = (const int*)  d_in[4];
    // d_in[5] = addressee (unused)
    const float* persona = (const float*)d_in[6];
    const float* W1 = (const float*)d_in[7];
    const float* U1 = (const float*)d_in[8];
    const float* b1 = (const float*)d_in[9];
    const float* W2 = (const float*)d_in[10];
    const float* U2 = (const float*)d_in[11];
    const float* b2 = (const float*)d_in[12];
    const float* W3 = (const float*)d_in[13];
    const float* U3 = (const float*)d_in[14];
    const float* b3 = (const float*)d_in[15];
    const float* W4 = (const float*)d_in[16];
    const float* U4 = (const float*)d_in[17];
    const float* b4 = (const float*)d_in[18];
    const float* Wd = (const float*)d_in[19];
    const float* bd = (const float*)d_in[20];

    float* out = (float*)d_out;

    // Resolve scratch symbol addresses (pure lookups; graph-capture safe)
    void *p_xh, *p_z, *p_h, *p_c, *p_wsum;
    cudaGetSymbolAddress(&p_xh,   g_xh);
    cudaGetSymbolAddress(&p_z,    g_z);
    cudaGetSymbolAddress(&p_h,    g_h);
    cudaGetSymbolAddress(&p_c,    g_c);
    cudaGetSymbolAddress(&p_wsum, g_wsum);
    float* xh   = (float*)p_xh;
    float* z    = (float*)p_z;
    float* h    = (float*)p_h;
    float* c    = (float*)p_c;
    float* wsum = (float*)p_wsum;

    // 1) Build [x | h0]
    build_xh_kernel<<<(Bn * XHW + 255) / 256, 256>>>(enc, word, persona, speaker, h0);

    // 2) Layer 1: z = x@W1 + b1 + h0@U1
    sgemm64_kernel<<<dim3(G4 / 64, Bn / 64), 256>>>(xh, XHW, W1, G4, b1, z, G4, XW, 0);
    sgemm64_kernel<<<dim3(G4 / 64, Bn / 64), 256>>>(xh + XW, XHW, U1, G4, nullptr, z, G4, Hn, 1);
    lstm_gates_kernel<<<(Bn * Hn + 255) / 256, 256>>>(z, c0, h, c);

    // 3) Layers 2..4: z = h @ (W+U) + b
    const float* Ws[3] = {W2, W3, W4};
    const float* Us[3] = {U2, U3, U4};
    const float* bs[3] = {b2, b3, b4};
    for (int l = 0; l < 3; l++) {
        add_w_kernel<<<(Hn * G4 + 255) / 256, 256>>>(Ws[l], Us[l]);
        sgemm64_kernel<<<dim3(G4 / 64, Bn / 64), 256>>>(h, Hn, wsum, G4, bs[l], z, G4, Hn, 0);
        lstm_gates_kernel<<<(Bn * Hn + 255) / 256, 256>>>(z, c, h, c);
    }

    // 4) Decoder: logits -> d_out, softmax in place
    sgemm64_kernel<<<dim3(Vn / 64, Bn / 64), 256>>>(h, Hn, Wd, Vn, bd, out, Vn, Hn, 0);
    softmax_rows_kernel<<<Bn, 256>>>(out);

    // 5) (h4, c4) into output tail if present
    if (out_size >= Bn * Vn + 2 * Bn * Hn) {
        copy_states_kernel<<<(Bn * Hn + 255) / 256, 256>>>(out + (size_t)Bn * Vn,
                                                           out + (size_t)Bn * Vn + Bn * Hn);
    }
}

// round 3
// speedup vs baseline: 2.6557x; 2.6557x over previous
#include <cuda_runtime.h>
#include <cuda_bf16.h>
#include <mma.h>
#include <math.h>
#include <cstdint>

using namespace nvcuda;

// -------------------------------------------------------------------------
// Problem dims
// -------------------------------------------------------------------------
constexpr int Bn = 256, Sn = 20, En = 512, Hn = 512, Vn = 32000;
constexpr int XW  = Sn * En + 2 * En;  // 11264
constexpr int KC1 = XW + Hn;           // 11776 (x | h0)
constexpr int G4  = 4 * Hn;            // 2048
constexpr int BK  = 32;

// -------------------------------------------------------------------------
// Static device scratch
// -------------------------------------------------------------------------
__device__ __align__(16) __nv_bfloat16 g_a1h[Bn * KC1];
__device__ __align__(16) __nv_bfloat16 g_a1l[Bn * KC1];
__device__ __align__(16) __nv_bfloat16 g_hh[Bn * Hn];
__device__ __align__(16) __nv_bfloat16 g_hl[Bn * Hn];
__device__ __align__(16) float g_zp[8 * Bn * G4];   // split-K partials (max 8)
__device__ __align__(16) float g_h[Bn * Hn];
__device__ __align__(16) float g_c[Bn * Hn];

// -------------------------------------------------------------------------
// Helpers
// -------------------------------------------------------------------------
__device__ __forceinline__ uint32_t pack_bf2(__nv_bfloat16 a, __nv_bfloat16 b) {
    __nv_bfloat162 t = __halves2bfloat162(a, b);
    return *reinterpret_cast<uint32_t*>(&t);
}

__device__ __forceinline__ void split_f(float v, __nv_bfloat16& hi, __nv_bfloat16& lo) {
    hi = __float2bfloat16(v);
    lo = __float2bfloat16(v - __bfloat162float(hi));
}

// -------------------------------------------------------------------------
// WMMA GEMM: C[128x128 tile] = A[M,K] @ B[K,N]
//   A given as hi/lo bf16 arrays (row-major, ld=lda).
//   B read as fp32 [K][N] (ld=ldb) and hi/lo split in the loader.
//   BMODE: 0 = B1 only; 1 = B1+B2 (elementwise); 2 = rows<XW from B1 else B2.
//   Split-K: blockIdx.z selects a K range; C is offset by z*Mtot*ldc
//   (partial buffers; reduction happens downstream). bias added when non-null.
// -------------------------------------------------------------------------
constexpr int SM_AH = 0;                 // 128 x 40 bf16 = 10240 B
constexpr int SM_AL = 10240;
constexpr int SM_BH = 20480;             // 32 x 136 bf16 = 8704 B
constexpr int SM_BL = 29184;
constexpr int SM_BYTES = 37888;

template<int BMODE>
__global__ void __launch_bounds__(256)
gemm_wmma(const __nv_bfloat16* __restrict__ Ah, const __nv_bfloat16* __restrict__ Al,
          int lda,
          const float* __restrict__ B1, const float* __restrict__ B2, int ldb,
          float* __restrict__ C, int ldc, const float* __restrict__ bias,
          int chunks)
{
    __shared__ __align__(16) char sm[SM_BYTES];
    __nv_bfloat16* sAh = (__nv_bfloat16*)(sm + SM_AH);
    __nv_bfloat16* sAl = (__nv_bfloat16*)(sm + SM_AL);
    __nv_bfloat16* sBh = (__nv_bfloat16*)(sm + SM_BH);
    __nv_bfloat16* sBl = (__nv_bfloat16*)(sm + SM_BL);

    const int tid = threadIdx.x;
    const int wid = tid >> 5;
    const int m0 = blockIdx.y * 128;
    const int n0 = blockIdx.x * 128;
    const int kbase = blockIdx.z * chunks * BK;
    C += (size_t)blockIdx.z * (size_t)(gridDim.y * 128) * ldc;

    // per-thread load coordinates
    const int ar = tid >> 2;            // A: 0..63 (+64)
    const int ac = (tid & 3) << 3;      // A col in elems (0,8,16,24)
    const int br = tid >> 5;            // B: 0..7 (+8,+16,+24)
    const int bc = (tid & 31) << 2;     // B col in elems (0..124)

    wmma::fragment<wmma::accumulator, 16, 16, 16, float> acc[2][4];
    #pragma unroll
    for (int i = 0; i < 2; i++)
        #pragma unroll
        for (int j = 0; j < 4; j++)
            wmma::fill_fragment(acc[i][j], 0.0f);

    uint4  rAh[2], rAl[2];
    float4 rB[4], rB2[4];

    auto load_regs = [&](int k0) {
        #pragma unroll
        for (int i = 0; i < 2; i++) {
            const size_t off = (size_t)(m0 + ar + i * 64) * lda + k0 + ac;
            rAh[i] = *reinterpret_cast<const uint4*>(Ah + off);
            rAl[i] = *reinterpret_cast<const uint4*>(Al + off);
        }
        const float* bp;
        if (BMODE == 2)
            bp = (k0 < XW) ? (B1 + (size_t)k0 * ldb) : (B2 + (size_t)(k0 - XW) * ldb);
        else
            bp = B1 + (size_t)k0 * ldb;
        #pragma unroll
        for (int i = 0; i < 4; i++) {
            const size_t off = (size_t)(br + i * 8) * ldb + n0 + bc;
            rB[i] = *reinterpret_cast<const float4*>(bp + off);
            if (BMODE == 1)
                rB2[i] = *reinterpret_cast<const float4*>(B2 + (size_t)(k0 + br + i * 8) * ldb + n0 + bc);
        }
    };

    auto store_smem = [&]() {
        #pragma unroll
        for (int i = 0; i < 2; i++) {
            const int off = (ar + i * 64) * 40 + ac;
            *reinterpret_cast<uint4*>(sAh + off) = rAh[i];
            *reinterpret_cast<uint4*>(sAl + off) = rAl[i];
        }
        #pragma unroll
        for (int i = 0; i < 4; i++) {
            float x0 = rB[i].x, x1 = rB[i].y, x2 = rB[i].z, x3 = rB[i].w;
            if (BMODE == 1) { x0 += rB2[i].x; x1 += rB2[i].y; x2 += rB2[i].z; x3 += rB2[i].w; }
            __nv_bfloat16 h0, l0, h1, l1, h2, l2, h3, l3;
            split_f(x0, h0, l0); split_f(x1, h1, l1);
            split_f(x2, h2, l2); split_f(x3, h3, l3);
            const int off = (br + i * 8) * 136 + bc;
            uint2 hv = make_uint2(pack_bf2(h0, h1), pack_bf2(h2, h3));
            uint2 lv = make_uint2(pack_bf2(l0, l1), pack_bf2(l2, l3));
            *reinterpret_cast<uint2*>(sBh + off) = hv;
            *reinterpret_cast<uint2*>(sBl + off) = lv;
        }
    };

    const int wm = (wid & 3) * 32;   // warp row offset in tile
    const int wn = (wid >> 2) * 64;  // warp col offset in tile

    load_regs(kbase);
    for (int c = 0; c < chunks; c++) {
        store_smem();
        __syncthreads();
        if (c + 1 < chunks) load_regs(kbase + (c + 1) * BK);

        #pragma unroll
        for (int kk = 0; kk < 2; kk++) {
            wmma::fragment<wmma::matrix_a, 16, 16, 16, __nv_bfloat16, wmma::row_major> fah[2], fal[2];
            wmma::fragment<wmma::matrix_b, 16, 16, 16, __nv_bfloat16, wmma::row_major> fbh[4], fbl[4];
            #pragma unroll
            for (int i = 0; i < 2; i++) {
                wmma::load_matrix_sync(fah[i], sAh + (wm + i * 16) * 40 + kk * 16, 40);
                wmma::load_matrix_sync(fal[i], sAl + (wm + i * 16) * 40 + kk * 16, 40);
            }
            #pragma unroll
            for (int j = 0; j < 4; j++) {
                wmma::load_matrix_sync(fbh[j], sBh + (kk * 16) * 136 + wn + j * 16, 136);
                wmma::load_matrix_sync(fbl[j], sBl + (kk * 16) * 136 + wn + j * 16, 136);
            }
            #pragma unroll
            for (int i = 0; i < 2; i++)
                #pragma unroll
                for (int j = 0; j < 4; j++) {
                    wmma::mma_sync(acc[i][j], fah[i], fbh[j], acc[i][j]);
                    wmma::mma_sync(acc[i][j], fah[i], fbl[j], acc[i][j]);
                    wmma::mma_sync(acc[i][j], fal[i], fbh[j], acc[i][j]);
                }
        }
        __syncthreads();
    }

    // Epilogue: stage each 16x16 frag through smem (reuses sAh region)
    float* stage = reinterpret_cast<float*>(sm) + wid * 256;
    const int lane = tid & 31;
    const int sr = lane >> 1;
    const int sc = (lane & 1) * 8;
    #pragma unroll
    for (int i = 0; i < 2; i++)
        #pragma unroll
        for (int j = 0; j < 4; j++) {
            wmma::store_matrix_sync(stage, acc[i][j], 16, wmma::mem_row_major);
            __syncwarp();
            const int grow = m0 + wm + i * 16 + sr;
            const int gcol = n0 + wn + j * 16 + sc;
            float* cp = C + (size_t)grow * ldc + gcol;
            if (bias) {
                #pragma unroll
                for (int q = 0; q < 8; q++) cp[q] = stage[sr * 16 + sc + q] + bias[gcol + q];
            } else {
                #pragma unroll
                for (int q = 0; q < 8; q++) cp[q] = stage[sr * 16 + sc + q];
            }
            __syncwarp();
        }
}

// -------------------------------------------------------------------------
// Build split-bf16 A for layer 1: [enc_flat | word | persona[speaker] | h0]
// -------------------------------------------------------------------------
__global__ void build_a1_kernel(const float* __restrict__ enc, const float* __restrict__ word,
                                const float* __restrict__ persona, const int* __restrict__ speaker,
                                const float* __restrict__ h0)
{
    int idx = blockIdx.x * blockDim.x + threadIdx.x;
    if (idx >= Bn * KC1) return;
    int b = idx / KC1, k = idx - b * KC1;
    float v;
    if (k < Sn * En)           v = enc[(size_t)b * Sn * En + k];
    else if (k < Sn * En + En) v = word[b * En + k - Sn * En];
    else if (k < XW)           v = persona[(size_t)speaker[b] * En + k - (Sn * En + En)];
    else                       v = h0[b * Hn + k - XW];
    __nv_bfloat16 hi, lo;
    split_f(v, hi, lo);
    g_a1h[idx] = hi;
    g_a1l[idx] = lo;
}

// -------------------------------------------------------------------------
// Gates: reduce split-K partials + bias, apply LSTM cell, emit h (fp32 + hi/lo)
// -------------------------------------------------------------------------
__device__ __forceinline__ float sigf(float x) { return 1.0f / (1.0f + expf(-x)); }

__global__ void gates_kernel(const float* __restrict__ zp, const float* __restrict__ bias,
                             int nsplit, const float* __restrict__ c_in,
                             float* __restrict__ h_out, float* __restrict__ c_out)
{
    int idx = blockIdx.x * blockDim.x + threadIdx.x;
    if (idx >= Bn * Hn) return;
    int b = idx >> 9, j = idx & (Hn - 1);
    float zg[4];
    #pragma unroll
    for (int g = 0; g < 4; g++) {
        float s = bias[g * Hn + j];
        for (int sp = 0; sp < nsplit; sp++)
            s += zp[(size_t)sp * Bn * G4 + (size_t)b * G4 + g * Hn + j];
        zg[g] = s;
    }
    float gi = sigf(zg[0]);
    float gf = sigf(zg[1]);
    float gg = fmaxf(zg[2], 0.f);
    float go = sigf(zg[3]);
    float c = gf * c_in[idx] + gi * gg;
    c_out[idx] = c;
    float h = go * fmaxf(c, 0.f);
    h_out[idx] = h;
    __nv_bfloat16 hi, lo;
    split_f(h, hi, lo);
    g_hh[idx] = hi;
    g_hl[idx] = lo;
}

// -------------------------------------------------------------------------
// Softmax (in place, one block / row)
// -------------------------------------------------------------------------
__global__ void softmax_rows_kernel(float* __restrict__ logits)
{
    __shared__ float red[8];
    __shared__ float bcast;
    const int b = blockIdx.x;
    float* row = logits + (size_t)b * Vn;
    const int tid = threadIdx.x;

    float m = -1e30f;
    for (int j = tid; j < Vn; j += 256) m = fmaxf(m, row[j]);
    #pragma unroll
    for (int o = 16; o; o >>= 1) m = fmaxf(m, __shfl_xor_sync(0xffffffffu, m, o));
    if ((tid & 31) == 0) red[tid >> 5] = m;
    __syncthreads();
    if (tid == 0) {
        float mm = red[0];
        #pragma unroll
        for (int i = 1; i < 8; i++) mm = fmaxf(mm, red[i]);
        bcast = mm;
    }
    __syncthreads();
    m = bcast;
    __syncthreads();

    float s = 0.f;
    for (int j = tid; j < Vn; j += 256) s += expf(row[j] - m);
    #pragma unroll
    for (int o = 16; o; o >>= 1) s += __shfl_xor_sync(0xffffffffu, s, o);
    if ((tid & 31) == 0) red[tid >> 5] = s;
    __syncthreads();
    if (tid == 0) {
        float ss = 0.f;
        #pragma unroll
        for (int i = 0; i < 8; i++) ss += red[i];
        bcast = ss;
    }
    __syncthreads();
    const float inv = 1.0f / bcast;
    for (int j = tid; j < Vn; j += 256) row[j] = expf(row[j] - m) * inv;
}

__global__ void copy_states_kernel(float* __restrict__ out_h, float* __restrict__ out_c)
{
    int idx = blockIdx.x * blockDim.x + threadIdx.x;
    if (idx < Bn * Hn) { out_h[idx] = g_h[idx]; out_c[idx] = g_c[idx]; }
}

// -------------------------------------------------------------------------
// Launch
// -------------------------------------------------------------------------
extern "C" void kernel_launch(void* const* d_in, const int* in_sizes, int n_in,
                              void* d_out, int out_size)
{
    const float* enc     = (const float*)d_in[0];
    const float* word    = (const float*)d_in[1];
    const float* h0      = (const float*)d_in[2];
    const float* c0      = (const float*)d_in[3];
    const int*   speaker = (const int*)  d_in[4];
    const float* persona = (const float*)d_in[6];
    const float* W1 = (const float*)d_in[7];
    const float* U1 = (const float*)d_in[8];
    const float* b1 = (const float*)d_in[9];
    const float* W2 = (const float*)d_in[10];
    const float* U2 = (const float*)d_in[11];
    const float* b2 = (const float*)d_in[12];
    const float* W3 = (const float*)d_in[13];
    const float* U3 = (const float*)d_in[14];
    const float* b3 = (const float*)d_in[15];
    const float* W4 = (const float*)d_in[16];
    const float* U4 = (const float*)d_in[17];
    const float* b4 = (const float*)d_in[18];
    const float* Wd = (const float*)d_in[19];
    const float* bd = (const float*)d_in[20];
    float* out = (float*)d_out;

    void *p_a1h, *p_a1l, *p_hh, *p_hl, *p_zp, *p_h, *p_c;
    cudaGetSymbolAddress(&p_a1h, g_a1h);
    cudaGetSymbolAddress(&p_a1l, g_a1l);
    cudaGetSymbolAddress(&p_hh,  g_hh);
    cudaGetSymbolAddress(&p_hl,  g_hl);
    cudaGetSymbolAddress(&p_zp,  g_zp);
    cudaGetSymbolAddress(&p_h,   g_h);
    cudaGetSymbolAddress(&p_c,   g_c);
    __nv_bfloat16* a1h = (__nv_bfloat16*)p_a1h;
    __nv_bfloat16* a1l = (__nv_bfloat16*)p_a1l;
    __nv_bfloat16* hh  = (__nv_bfloat16*)p_hh;
    __nv_bfloat16* hl  = (__nv_bfloat16*)p_hl;
    float* zp = (float*)p_zp;
    float* h  = (float*)p_h;
    float* c  = (float*)p_c;

    // Layer 1: A = [x|h0] (K=11776), B = rows<XW ? W1 : U1. split-K = 8.
    build_a1_kernel<<<(Bn * KC1 + 255) / 256, 256>>>(enc, word, persona, speaker, h0);
    gemm_wmma<2><<<dim3(G4 / 128, Bn / 128, 8), 256>>>(
        a1h, a1l, KC1, W1, U1, G4, zp, G4, nullptr, (KC1 / BK) / 8);
    gates_kernel<<<(Bn * Hn + 255) / 256, 256>>>(zp, b1, 8, c0, h, c);

    // Layers 2..4: B = W+U (K=512), split-K = 4.
    const float* Ws[3] = {W2, W3, W4};
    const float* Us[3] = {U2, U3, U4};
    const float* bs[3] = {b2, b3, b4};
    for (int l = 0; l < 3; l++) {
        gemm_wmma<1><<<dim3(G4 / 128, Bn / 128, 4), 256>>>(
            hh, hl, Hn, Ws[l], Us[l], G4, zp, G4, nullptr, (Hn / BK) / 4);
        gates_kernel<<<(Bn * Hn + 255) / 256, 256>>>(zp, bs[l], 4, c, h, c);
    }

    // Decoder (N=32000, K=512) + softmax
    gemm_wmma<0><<<dim3(Vn / 128, Bn / 128, 1), 256>>>(
        hh, hl, Hn, Wd, nullptr, Vn, out, Vn, bd, Hn / BK);
    softmax_rows_kernel<<<Bn, 256>>>(out);

    if (out_size >= Bn * Vn + 2 * Bn * Hn) {
        copy_states_kernel<<<(Bn * Hn + 255) / 256, 256>>>(out + (size_t)Bn * Vn,
                                                           out + (size_t)Bn * Vn + Bn * Hn);
    }
}

// round 4
// speedup vs baseline: 3.4980x; 1.3172x over previous
#include <cuda_runtime.h>
#include <cuda_bf16.h>
#include <mma.h>
#include <math.h>
#include <cstdint>

using namespace nvcuda;

// -------------------------------------------------------------------------
// Problem dims
// -------------------------------------------------------------------------
constexpr int Bn = 256, Sn = 20, En = 512, Hn = 512, Vn = 32000;
constexpr int XW  = Sn * En + 2 * En;  // 11264
constexpr int KC1 = XW + Hn;           // 11776 (x | h0)
constexpr int G4  = 4 * Hn;            // 2048
constexpr int BK  = 64;

// -------------------------------------------------------------------------
// Static device scratch
// -------------------------------------------------------------------------
__device__ __align__(16) __nv_bfloat16 g_a1h[Bn * KC1];
__device__ __align__(16) __nv_bfloat16 g_a1l[Bn * KC1];
__device__ __align__(16) __nv_bfloat16 g_hh[Bn * Hn];
__device__ __align__(16) __nv_bfloat16 g_hl[Bn * Hn];
__device__ __align__(16) float g_zp[8 * Bn * G4];   // split-K partials
__device__ __align__(16) float g_h[Bn * Hn];
__device__ __align__(16) float g_c[Bn * Hn];
__device__ float g_rowmax[Bn];
__device__ float g_rowsum[Bn];

// -------------------------------------------------------------------------
// Helpers
// -------------------------------------------------------------------------
__device__ __forceinline__ uint32_t smem_u32(const void* p) {
    uint32_t a;
    asm("{ .reg .u64 t; cvta.to.shared.u64 t, %1; cvt.u32.u64 %0, t; }" : "=r"(a) : "l"(p));
    return a;
}
__device__ __forceinline__ void cp16(uint32_t s, const void* g) {
    asm volatile("cp.async.cg.shared.global [%0], [%1], 16;" :: "r"(s), "l"(g));
}
#define CP_COMMIT() asm volatile("cp.async.commit_group;" ::: "memory")
#define CP_WAIT1()  asm volatile("cp.async.wait_group 1;" ::: "memory")

__device__ __forceinline__ uint32_t pack_bf2(float a, float b) {
    __nv_bfloat162 t = __floats2bfloat162_rn(a, b);
    return *reinterpret_cast<uint32_t*>(&t);
}
__device__ __forceinline__ void split_f(float v, __nv_bfloat16& hi, __nv_bfloat16& lo) {
    hi = __float2bfloat16(v);
    lo = __float2bfloat16(v - __bfloat162float(hi));
}

// -------------------------------------------------------------------------
// SMEM layout (dynamic): A 3 slots x {hi,lo} 128x(64 pad 72) bf16,
//                        B 2 bufs  x {hi,lo} 64x(128 pad 136) bf16
// -------------------------------------------------------------------------
constexpr int A_PITCH = 72;                       // elems; row = 144 B
constexpr int A_ARR   = 128 * A_PITCH * 2;        // 18432 B
constexpr int A_SLOT  = 2 * A_ARR;                // 36864 B
constexpr int OFF_B   = 3 * A_SLOT;               // 110592
constexpr int B_PITCH = 136;                      // elems; row = 272 B
constexpr int B_ARR   = 64 * B_PITCH * 2;         // 17408 B
constexpr int B_BUF   = 2 * B_ARR;                // 34816 B
constexpr int SMEM_TOTAL = OFF_B + 2 * B_BUF;     // 180224 B

// -------------------------------------------------------------------------
// GEMM: C[M,N] = A @ B, A = (Ah + Al) bf16 row-major, B fp32 [K][N].
// 3-term split-bf16: hi*hi + hi*lo + lo*hi.
// BMODE: 0 = B1; 1 = B1 + B2 elementwise; 2 = rows<XW from B1 else B2.
// split-K via blockIdx.z into partial buffers (C += z*Mtot*ldc).
// -------------------------------------------------------------------------
template<int BMODE>
__global__ void __launch_bounds__(256)
gemm_bf3(const __nv_bfloat16* __restrict__ Ah, const __nv_bfloat16* __restrict__ Al,
         int lda,
         const float* __restrict__ B1, const float* __restrict__ B2, int ldb,
         float* __restrict__ C, int ldc, int chunks)
{
    extern __shared__ __align__(16) char smem[];
    const uint32_t sbase = smem_u32(smem);

    const int tid = threadIdx.x;
    const int wid = tid >> 5;
    const int m0 = blockIdx.y * 128;
    const int n0 = blockIdx.x * 128;
    const int kbase = blockIdx.z * chunks * BK;
    C += (size_t)blockIdx.z * (size_t)(gridDim.y * 128) * ldc;

    // A cp.async coords: 4 granules of 16B per array per chunk per thread
    const int a_row = tid >> 1;            // base rows: tid>>3 pattern: t=tid+i*256
    (void)a_row;
    // B load coords: 8 float4 per thread
    const int b_r = tid >> 5;              // +i*8
    const int b_c = (tid & 31) << 2;

    auto issueA = [&](int c, int slot) {
        const int k0 = kbase + c * BK;
        #pragma unroll
        for (int i = 0; i < 4; i++) {
            const int t = tid + i * 256;
            const int row = t >> 3, g = t & 7;
            const size_t goff = (size_t)(m0 + row) * lda + k0 + g * 8;
            const uint32_t soff = sbase + slot * A_SLOT + row * 144 + g * 16;
            cp16(soff,         Ah + goff);
            cp16(soff + A_ARR, Al + goff);
        }
    };

    float4 rB[8], rB2[8];
    auto loadB = [&](int c) {
        const int k0 = kbase + c * BK;
        const float* bp;
        if (BMODE == 2)
            bp = (k0 < XW) ? (B1 + (size_t)k0 * ldb) : (B2 + (size_t)(k0 - XW) * ldb);
        else
            bp = B1 + (size_t)k0 * ldb;
        #pragma unroll
        for (int i = 0; i < 8; i++) {
            const size_t off = (size_t)(b_r + i * 8) * ldb + n0 + b_c;
            rB[i] = *reinterpret_cast<const float4*>(bp + off);
            if (BMODE == 1)
                rB2[i] = *reinterpret_cast<const float4*>(B2 + (size_t)(k0 + b_r + i * 8) * ldb + n0 + b_c);
        }
    };
    auto storeB = [&](int buf) {
        char* bb = smem + OFF_B + buf * B_BUF;
        #pragma unroll
        for (int i = 0; i < 8; i++) {
            float x0 = rB[i].x, x1 = rB[i].y, x2 = rB[i].z, x3 = rB[i].w;
            if (BMODE == 1) { x0 += rB2[i].x; x1 += rB2[i].y; x2 += rB2[i].z; x3 += rB2[i].w; }
            __nv_bfloat16 h0, l0, h1, l1, h2, l2, h3, l3;
            split_f(x0, h0, l0); split_f(x1, h1, l1);
            split_f(x2, h2, l2); split_f(x3, h3, l3);
            const int off = (b_r + i * 8) * 272 + b_c * 2;   // bytes
            uint2 hv, lv;
            hv.x = pack_bf2(__bfloat162float(h0), __bfloat162float(h1));
            hv.y = pack_bf2(__bfloat162float(h2), __bfloat162float(h3));
            lv.x = pack_bf2(__bfloat162float(l0), __bfloat162float(l1));
            lv.y = pack_bf2(__bfloat162float(l2), __bfloat162float(l3));
            *reinterpret_cast<uint2*>(bb + off)         = hv;
            *reinterpret_cast<uint2*>(bb + B_ARR + off) = lv;
        }
    };

    wmma::fragment<wmma::accumulator, 16, 16, 16, float> acc[2][4];
    #pragma unroll
    for (int i = 0; i < 2; i++)
        #pragma unroll
        for (int j = 0; j < 4; j++)
            wmma::fill_fragment(acc[i][j], 0.0f);

    const int wm = (wid & 3) * 32;
    const int wn = (wid >> 2) * 64;

    // Prologue
    issueA(0, 0); CP_COMMIT();
    if (chunks > 1) issueA(1, 1);
    CP_COMMIT();
    loadB(0);
    storeB(0);

    for (int c = 0; c < chunks; c++) {
        CP_WAIT1();            // A(c) arrived (A(c+1) may be in flight)
        __syncthreads();       // A(c), B(c) visible; MMA(c-1) done by all warps

        if (c + 2 < chunks) issueA(c + 2, (c + 2) % 3);
        CP_COMMIT();           // exactly one group per iteration
        if (c + 1 < chunks) loadB(c + 1);

        // MMA on chunk c
        const __nv_bfloat16* sAh = (const __nv_bfloat16*)(smem + (c % 3) * A_SLOT);
        const __nv_bfloat16* sAl = (const __nv_bfloat16*)(smem + (c % 3) * A_SLOT + A_ARR);
        const __nv_bfloat16* sBh = (const __nv_bfloat16*)(smem + OFF_B + (c & 1) * B_BUF);
        const __nv_bfloat16* sBl = (const __nv_bfloat16*)(smem + OFF_B + (c & 1) * B_BUF + B_ARR);
        #pragma unroll
        for (int kk = 0; kk < 4; kk++) {
            wmma::fragment<wmma::matrix_a, 16, 16, 16, __nv_bfloat16, wmma::row_major> fah[2], fal[2];
            #pragma unroll
            for (int i = 0; i < 2; i++) {
                wmma::load_matrix_sync(fah[i], sAh + (wm + i * 16) * A_PITCH + kk * 16, A_PITCH);
                wmma::load_matrix_sync(fal[i], sAl + (wm + i * 16) * A_PITCH + kk * 16, A_PITCH);
            }
            #pragma unroll
            for (int j = 0; j < 4; j++) {
                wmma::fragment<wmma::matrix_b, 16, 16, 16, __nv_bfloat16, wmma::row_major> fbh, fbl;
                wmma::load_matrix_sync(fbh, sBh + (kk * 16) * B_PITCH + wn + j * 16, B_PITCH);
                wmma::load_matrix_sync(fbl, sBl + (kk * 16) * B_PITCH + wn + j * 16, B_PITCH);
                #pragma unroll
                for (int i = 0; i < 2; i++) {
                    wmma::mma_sync(acc[i][j], fah[i], fbh, acc[i][j]);
                    wmma::mma_sync(acc[i][j], fah[i], fbl, acc[i][j]);
                    wmma::mma_sync(acc[i][j], fal[i], fbh, acc[i][j]);
                }
            }
        }

        if (c + 1 < chunks) storeB((c + 1) & 1);
    }

    // Epilogue: direct stores (no bias — folded downstream)
    #pragma unroll
    for (int i = 0; i < 2; i++)
        #pragma unroll
        for (int j = 0; j < 4; j++) {
            float* cp = C + (size_t)(m0 + wm + i * 16) * ldc + n0 + wn + j * 16;
            wmma::store_matrix_sync(cp, acc[i][j], ldc, wmma::mem_row_major);
        }
}

// -------------------------------------------------------------------------
// Build split-bf16 A for layer 1
// -------------------------------------------------------------------------
__global__ void build_a1_kernel(const float* __restrict__ enc, const float* __restrict__ word,
                                const float* __restrict__ persona, const int* __restrict__ speaker,
                                const float* __restrict__ h0)
{
    int idx = blockIdx.x * blockDim.x + threadIdx.x;
    if (idx >= Bn * KC1) return;
    int b = idx / KC1, k = idx - b * KC1;
    float v;
    if (k < Sn * En)           v = enc[(size_t)b * Sn * En + k];
    else if (k < Sn * En + En) v = word[b * En + k - Sn * En];
    else if (k < XW)           v = persona[(size_t)speaker[b] * En + k - (Sn * En + En)];
    else                       v = h0[b * Hn + k - XW];
    __nv_bfloat16 hi, lo;
    split_f(v, hi, lo);
    g_a1h[idx] = hi;
    g_a1l[idx] = lo;
}

// -------------------------------------------------------------------------
// Gates: reduce split-K partials + bias, LSTM cell, emit h (fp32 + hi/lo)
// -------------------------------------------------------------------------
__device__ __forceinline__ float sigf(float x) { return 1.0f / (1.0f + __expf(-x)); }

__global__ void gates_kernel(const float* __restrict__ zp, const float* __restrict__ bias,
                             int nsplit, const float* __restrict__ c_in,
                             float* __restrict__ h_out, float* __restrict__ c_out)
{
    int idx = blockIdx.x * blockDim.x + threadIdx.x;
    if (idx >= Bn * Hn) return;
    int b = idx >> 9, j = idx & (Hn - 1);
    float zg[4];
    #pragma unroll
    for (int g = 0; g < 4; g++) {
        float s = bias[g * Hn + j];
        for (int sp = 0; sp < nsplit; sp++)
            s += zp[(size_t)sp * Bn * G4 + (size_t)b * G4 + g * Hn + j];
        zg[g] = s;
    }
    float gi = sigf(zg[0]);
    float gf = sigf(zg[1]);
    float gg = fmaxf(zg[2], 0.f);
    float go = sigf(zg[3]);
    float c = gf * c_in[idx] + gi * gg;
    c_out[idx] = c;
    float h = go * fmaxf(c, 0.f);
    h_out[idx] = h;
    __nv_bfloat16 hi, lo;
    split_f(h, hi, lo);
    g_hh[idx] = hi;
    g_hl[idx] = lo;
}

// -------------------------------------------------------------------------
// Softmax, 3 passes, exp computed once. bias bd folded here.
// -------------------------------------------------------------------------
__global__ void smax_max_kernel(const float* __restrict__ logits, const float* __restrict__ bd)
{
    __shared__ float red[16];
    const int b = blockIdx.x;
    const float* row = logits + (size_t)b * Vn;
    const int tid = threadIdx.x;
    float m = -1e30f;
    for (int j = tid; j < Vn; j += 512) m = fmaxf(m, row[j] + bd[j]);
    #pragma unroll
    for (int o = 16; o; o >>= 1) m = fmaxf(m, __shfl_xor_sync(0xffffffffu, m, o));
    if ((tid & 31) == 0) red[tid >> 5] = m;
    __syncthreads();
    if (tid < 32) {
        float mm = (tid < 16) ? red[tid] : -1e30f;
        #pragma unroll
        for (int o = 8; o; o >>= 1) mm = fmaxf(mm, __shfl_xor_sync(0xffffffffu, mm, o));
        if (tid == 0) g_rowmax[b] = mm;
    }
}

__global__ void smax_exp_kernel(float* __restrict__ logits, const float* __restrict__ bd)
{
    __shared__ float red[16];
    const int b = blockIdx.x;
    float* row = logits + (size_t)b * Vn;
    const int tid = threadIdx.x;
    const float m = g_rowmax[b];
    float s = 0.f;
    for (int j = tid; j < Vn; j += 512) {
        float e = __expf(row[j] + bd[j] - m);
        row[j] = e;
        s += e;
    }
    #pragma unroll
    for (int o = 16; o; o >>= 1) s += __shfl_xor_sync(0xffffffffu, s, o);
    if ((tid & 31) == 0) red[tid >> 5] = s;
    __syncthreads();
    if (tid < 32) {
        float ss = (tid < 16) ? red[tid] : 0.f;
        #pragma unroll
        for (int o = 8; o; o >>= 1) ss += __shfl_xor_sync(0xffffffffu, ss, o);
        if (tid == 0) g_rowsum[b] = ss;
    }
}

__global__ void smax_scale_kernel(float* __restrict__ logits)
{
    const int b = blockIdx.x;
    float* row = logits + (size_t)b * Vn;
    const float inv = 1.0f / g_rowsum[b];
    for (int j = threadIdx.x; j < Vn; j += 512) row[j] *= inv;
}

// -------------------------------------------------------------------------
// Launch
// -------------------------------------------------------------------------
extern "C" void kernel_launch(void* const* d_in, const int* in_sizes, int n_in,
                              void* d_out, int out_size)
{
    const float* enc     = (const float*)d_in[0];
    const float* word    = (const float*)d_in[1];
    const float* h0      = (const float*)d_in[2];
    const float* c0      = (const float*)d_in[3];
    const int*   speaker = (const int*)  d_in[4];
    const float* persona = (const float*)d_in[6];
    const float* W1 = (const float*)d_in[7];
    const float* U1 = (const float*)d_in[8];
    const float* b1 = (const float*)d_in[9];
    const float* W2 = (const float*)d_in[10];
    const float* U2 = (const float*)d_in[11];
    const float* b2 = (const float*)d_in[12];
    const float* W3 = (const float*)d_in[13];
    const float* U3 = (const float*)d_in[14];
    const float* b3 = (const float*)d_in[15];
    const float* W4 = (const float*)d_in[16];
    const float* U4 = (const float*)d_in[17];
    const float* b4 = (const float*)d_in[18];
    const float* Wd = (const float*)d_in[19];
    const float* bd = (const float*)d_in[20];
    float* out = (float*)d_out;

    static bool attr_done = false;
    if (!attr_done) {
        cudaFuncSetAttribute(gemm_bf3<0>, cudaFuncAttributeMaxDynamicSharedMemorySize, SMEM_TOTAL);
        cudaFuncSetAttribute(gemm_bf3<1>, cudaFuncAttributeMaxDynamicSharedMemorySize, SMEM_TOTAL);
        cudaFuncSetAttribute(gemm_bf3<2>, cudaFuncAttributeMaxDynamicSharedMemorySize, SMEM_TOTAL);
        attr_done = true;
    }

    void *p_a1h, *p_a1l, *p_hh, *p_hl, *p_zp, *p_h, *p_c;
    cudaGetSymbolAddress(&p_a1h, g_a1h);
    cudaGetSymbolAddress(&p_a1l, g_a1l);
    cudaGetSymbolAddress(&p_hh,  g_hh);
    cudaGetSymbolAddress(&p_hl,  g_hl);
    cudaGetSymbolAddress(&p_zp,  g_zp);
    cudaGetSymbolAddress(&p_h,   g_h);
    cudaGetSymbolAddress(&p_c,   g_c);
    __nv_bfloat16* a1h = (__nv_bfloat16*)p_a1h;
    __nv_bfloat16* a1l = (__nv_bfloat16*)p_a1l;
    __nv_bfloat16* hh  = (__nv_bfloat16*)p_hh;
    __nv_bfloat16* hl  = (__nv_bfloat16*)p_hl;
    float* zp = (float*)p_zp;
    float* h  = (float*)p_h;
    float* c  = (float*)p_c;

    float* out_h = out + (size_t)Bn * Vn;
    float* out_c = out_h + (size_t)Bn * Hn;
    const bool has_tail = (out_size >= Bn * Vn + 2 * Bn * Hn);

    // Layer 1 (K=11776, split-K 8, 23 chunks each)
    build_a1_kernel<<<(Bn * KC1 + 255) / 256, 256>>>(enc, word, persona, speaker, h0);
    gemm_bf3<2><<<dim3(G4 / 128, Bn / 128, 8), 256, SMEM_TOTAL>>>(
        a1h, a1l, KC1, W1, U1, G4, zp, G4, KC1 / (BK * 8));
    gates_kernel<<<(Bn * Hn + 255) / 256, 256>>>(zp, b1, 8, c0, h, c);

    // Layers 2..4 (K=512, split-K 4, 2 chunks each)
    const float* Ws[3] = {W2, W3, W4};
    const float* Us[3] = {U2, U3, U4};
    const float* bs[3] = {b2, b3, b4};
    for (int l = 0; l < 3; l++) {
        gemm_bf3<1><<<dim3(G4 / 128, Bn / 128, 4), 256, SMEM_TOTAL>>>(
            hh, hl, Hn, Ws[l], Us[l], G4, zp, G4, Hn / (BK * 4));
        const bool last = (l == 2) && has_tail;
        gates_kernel<<<(Bn * Hn + 255) / 256, 256>>>(zp, bs[l], 4, c,
                                                     last ? out_h : h,
                                                     last ? out_c : c);
    }

    // Decoder (N=32000, K=512, 8 chunks) + softmax (bias folded)
    gemm_bf3<0><<<dim3(Vn / 128, Bn / 128, 1), 256, SMEM_TOTAL>>>(
        hh, hl, Hn, Wd, nullptr, Vn, out, Vn, Hn / BK);
    smax_max_kernel<<<Bn, 512>>>(out, bd);
    smax_exp_kernel<<<Bn, 512>>>(out, bd);
    smax_scale_kernel<<<Bn, 512>>>(out);
}

// round 6
// speedup vs baseline: 3.5365x; 1.0110x over previous
#include <cuda_runtime.h>
#include <cuda_bf16.h>
#include <mma.h>
#include <math.h>
#include <cstdint>

using namespace nvcuda;

// -------------------------------------------------------------------------
// Problem dims
// -------------------------------------------------------------------------
constexpr int Bn = 256, Sn = 20, En = 512, Hn = 512, Vn = 32000;
constexpr int XW  = Sn * En + 2 * En;  // 11264
constexpr int KC1 = XW + Hn;           // 11776 (x | h0)
constexpr int G4  = 4 * Hn;            // 2048
constexpr int BK  = 64;

// -------------------------------------------------------------------------
// Static device scratch
// -------------------------------------------------------------------------
__device__ __align__(16) __nv_bfloat16 g_a1h[Bn * KC1];
__device__ __align__(16) __nv_bfloat16 g_a1l[Bn * KC1];
__device__ __align__(16) __nv_bfloat16 g_hh[Bn * Hn];
__device__ __align__(16) __nv_bfloat16 g_hl[Bn * Hn];
__device__ __align__(16) float g_zp[4 * Bn * G4];   // split-K partials
__device__ __align__(16) float g_h[Bn * Hn];
__device__ __align__(16) float g_c[Bn * Hn];
__device__ float g_rowmax[Bn];
__device__ float g_rowsum[Bn];

// -------------------------------------------------------------------------
// Helpers
// -------------------------------------------------------------------------
__device__ __forceinline__ uint32_t smem_u32(const void* p) {
    uint32_t a;
    asm("{ .reg .u64 t; cvta.to.shared.u64 t, %1; cvt.u32.u64 %0, t; }" : "=r"(a) : "l"(p));
    return a;
}
__device__ __forceinline__ void cp16(uint32_t s, const void* g) {
    asm volatile("cp.async.cg.shared.global [%0], [%1], 16;" :: "r"(s), "l"(g));
}
#define CP_COMMIT() asm volatile("cp.async.commit_group;" ::: "memory")
#define CP_WAIT1()  asm volatile("cp.async.wait_group 1;" ::: "memory")

__device__ __forceinline__ uint32_t pack_bf2f(float a, float b) {
    __nv_bfloat162 t = __floats2bfloat162_rn(a, b);
    return *reinterpret_cast<uint32_t*>(&t);
}
__device__ __forceinline__ void split_f(float v, float& hi, float& lo) {
    __nv_bfloat16 h = __float2bfloat16(v);
    hi = __bfloat162float(h);
    lo = v - hi;
}

// -------------------------------------------------------------------------
// SMEM layout: A 3 slots x {hi,lo} 128x(64 pad 72) bf16,
//              B 2 bufs  x {hi,lo} 64x(128 pad 136) bf16
// -------------------------------------------------------------------------
constexpr int A_PITCH = 72;                       // elems; row = 144 B
constexpr int A_ARR   = 128 * A_PITCH * 2;        // 18432 B
constexpr int A_SLOT  = 2 * A_ARR;                // 36864 B
constexpr int OFF_B   = 3 * A_SLOT;               // 110592
constexpr int B_PITCH = 136;                      // elems; row = 272 B
constexpr int B_ARR   = 64 * B_PITCH * 2;         // 17408 B
constexpr int B_BUF   = 2 * B_ARR;                // 34816 B
constexpr int SMEM_TOTAL = OFF_B + 2 * B_BUF;     // 180224 B

// -------------------------------------------------------------------------
// GEMM: C[M,N] = A @ B; A = (Ah+Al) bf16 row-major; B fp32 [K][N].
// 3-term split-bf16 (hi*hi + hi*lo + lo*hi). 512 threads, warp tile 32x32.
// BMODE: 0 = B1; 1 = B1+B2 elementwise; 2 = rows<XW from B1 else B2.
// split-K via blockIdx.z into partial buffers.
// -------------------------------------------------------------------------
template<int BMODE>
__global__ void __launch_bounds__(512)
gemm_bf3(const __nv_bfloat16* __restrict__ Ah, const __nv_bfloat16* __restrict__ Al,
         int lda,
         const float* __restrict__ B1, const float* __restrict__ B2, int ldb,
         float* __restrict__ C, int ldc, int chunks)
{
    extern __shared__ __align__(16) char smem[];
    const uint32_t sbase = smem_u32(smem);

    const int tid = threadIdx.x;
    const int wid = tid >> 5;
    const int m0 = blockIdx.y * 128;
    const int n0 = blockIdx.x * 128;
    const int kbase = blockIdx.z * chunks * BK;
    C += (size_t)blockIdx.z * (size_t)(gridDim.y * 128) * ldc;

    // A: rows {tid>>3, tid>>3 + 64}, granule tid&7 (8 x 16B per 128B row)
    const int a_row = tid >> 3;          // 0..63
    const int a_g   = tid & 7;           // 0..7
    // B: 4 float4 per thread. 64 rows x 32 float4
    const int b_r = tid >> 5;            // +i*16
    const int b_c = (tid & 31) << 2;

    auto issueA = [&](int c, int slot) {
        const int k0 = kbase + c * BK;
        #pragma unroll
        for (int i = 0; i < 2; i++) {
            const int row = a_row + i * 64;
            const size_t goff = (size_t)(m0 + row) * lda + k0 + a_g * 8;
            const uint32_t soff = sbase + slot * A_SLOT + row * 144 + a_g * 16;
            cp16(soff,         Ah + goff);
            cp16(soff + A_ARR, Al + goff);
        }
    };

    float4 rB[4], rB2[4];
    auto loadB = [&](int c) {
        const int k0 = kbase + c * BK;
        const float* bp;
        if (BMODE == 2)
            bp = (k0 < XW) ? (B1 + (size_t)k0 * ldb) : (B2 + (size_t)(k0 - XW) * ldb);
        else
            bp = B1 + (size_t)k0 * ldb;
        #pragma unroll
        for (int i = 0; i < 4; i++) {
            const size_t off = (size_t)(b_r + i * 16) * ldb + n0 + b_c;
            rB[i] = *reinterpret_cast<const float4*>(bp + off);
            if (BMODE == 1)
                rB2[i] = *reinterpret_cast<const float4*>(B2 + (size_t)(k0 + b_r + i * 16) * ldb + n0 + b_c);
        }
    };
    auto storeB = [&](int buf) {
        char* bb = smem + OFF_B + buf * B_BUF;
        #pragma unroll
        for (int i = 0; i < 4; i++) {
            float x0 = rB[i].x, x1 = rB[i].y, x2 = rB[i].z, x3 = rB[i].w;
            if (BMODE == 1) { x0 += rB2[i].x; x1 += rB2[i].y; x2 += rB2[i].z; x3 += rB2[i].w; }
            float h0, l0, h1, l1, h2, l2, h3, l3;
            split_f(x0, h0, l0); split_f(x1, h1, l1);
            split_f(x2, h2, l2); split_f(x3, h3, l3);
            const int off = (b_r + i * 16) * 272 + b_c * 2;   // bytes
            uint2 hv, lv;
            hv.x = pack_bf2f(h0, h1); hv.y = pack_bf2f(h2, h3);
            lv.x = pack_bf2f(l0, l1); lv.y = pack_bf2f(l2, l3);
            *reinterpret_cast<uint2*>(bb + off)         = hv;
            *reinterpret_cast<uint2*>(bb + B_ARR + off) = lv;
        }
    };

    wmma::fragment<wmma::accumulator, 16, 16, 16, float> acc[2][2];
    #pragma unroll
    for (int i = 0; i < 2; i++)
        #pragma unroll
        for (int j = 0; j < 2; j++)
            wmma::fill_fragment(acc[i][j], 0.0f);

    const int wm = (wid & 3) * 32;
    const int wn = (wid >> 2) * 32;

    // Prologue
    issueA(0, 0); CP_COMMIT();
    if (chunks > 1) issueA(1, 1);
    CP_COMMIT();
    loadB(0);
    storeB(0);

    for (int c = 0; c < chunks; c++) {
        CP_WAIT1();            // A(c) landed (A(c+1) may be in flight)
        __syncthreads();

        if (c + 2 < chunks) issueA(c + 2, (c + 2) % 3);
        CP_COMMIT();
        if (c + 1 < chunks) loadB(c + 1);

        const __nv_bfloat16* sAh = (const __nv_bfloat16*)(smem + (c % 3) * A_SLOT);
        const __nv_bfloat16* sAl = (const __nv_bfloat16*)(smem + (c % 3) * A_SLOT + A_ARR);
        const __nv_bfloat16* sBh = (const __nv_bfloat16*)(smem + OFF_B + (c & 1) * B_BUF);
        const __nv_bfloat16* sBl = (const __nv_bfloat16*)(smem + OFF_B + (c & 1) * B_BUF + B_ARR);
        #pragma unroll
        for (int kk = 0; kk < 4; kk++) {
            wmma::fragment<wmma::matrix_a, 16, 16, 16, __nv_bfloat16, wmma::row_major> fah[2], fal[2];
            wmma::fragment<wmma::matrix_b, 16, 16, 16, __nv_bfloat16, wmma::row_major> fbh[2], fbl[2];
            #pragma unroll
            for (int i = 0; i < 2; i++) {
                wmma::load_matrix_sync(fah[i], sAh + (wm + i * 16) * A_PITCH + kk * 16, A_PITCH);
                wmma::load_matrix_sync(fal[i], sAl + (wm + i * 16) * A_PITCH + kk * 16, A_PITCH);
            }
            #pragma unroll
            for (int j = 0; j < 2; j++) {
                wmma::load_matrix_sync(fbh[j], sBh + (kk * 16) * B_PITCH + wn + j * 16, B_PITCH);
                wmma::load_matrix_sync(fbl[j], sBl + (kk * 16) * B_PITCH + wn + j * 16, B_PITCH);
            }
            #pragma unroll
            for (int i = 0; i < 2; i++)
                #pragma unroll
                for (int j = 0; j < 2; j++) {
                    wmma::mma_sync(acc[i][j], fah[i], fbh[j], acc[i][j]);
                    wmma::mma_sync(acc[i][j], fah[i], fbl[j], acc[i][j]);
                    wmma::mma_sync(acc[i][j], fal[i], fbh[j], acc[i][j]);
                }
        }

        if (c + 1 < chunks) storeB((c + 1) & 1);
    }

    // Epilogue: direct stores (bias folded downstream)
    #pragma unroll
    for (int i = 0; i < 2; i++)
        #pragma unroll
        for (int j = 0; j < 2; j++) {
            float* cp = C + (size_t)(m0 + wm + i * 16) * ldc + n0 + wn + j * 16;
            wmma::store_matrix_sync(cp, acc[i][j], ldc, wmma::mem_row_major);
        }
}

// -------------------------------------------------------------------------
// Build split-bf16 A for layer 1
// -------------------------------------------------------------------------
__global__ void build_a1_kernel(const float* __restrict__ enc, const float* __restrict__ word,
                                const float* __restrict__ persona, const int* __restrict__ speaker,
                                const float* __restrict__ h0)
{
    int idx = blockIdx.x * blockDim.x + threadIdx.x;
    if (idx >= Bn * KC1) return;
    int b = idx / KC1, k = idx - b * KC1;
    float v;
    if (k < Sn * En)           v = enc[(size_t)b * Sn * En + k];
    else if (k < Sn * En + En) v = word[b * En + k - Sn * En];
    else if (k < XW)           v = persona[(size_t)speaker[b] * En + k - (Sn * En + En)];
    else                       v = h0[b * Hn + k - XW];
    __nv_bfloat16 hi = __float2bfloat16(v);
    g_a1h[idx] = hi;
    g_a1l[idx] = __float2bfloat16(v - __bfloat162float(hi));
}

// -------------------------------------------------------------------------
// Gates: reduce split-K partials + bias, LSTM cell, emit h (fp32 + hi/lo)
// -------------------------------------------------------------------------
__device__ __forceinline__ float sigf(float x) { return 1.0f / (1.0f + __expf(-x)); }

__global__ void gates_kernel(const float* __restrict__ zp, const float* __restrict__ bias,
                             int nsplit, const float* __restrict__ c_in,
                             float* __restrict__ h_out, float* __restrict__ c_out)
{
    int idx = blockIdx.x * blockDim.x + threadIdx.x;
    if (idx >= Bn * Hn) return;
    int b = idx >> 9, j = idx & (Hn - 1);
    float zg[4];
    #pragma unroll
    for (int g = 0; g < 4; g++) {
        float s = bias[g * Hn + j];
        for (int sp = 0; sp < nsplit; sp++)
            s += zp[(size_t)sp * Bn * G4 + (size_t)b * G4 + g * Hn + j];
        zg[g] = s;
    }
    float gi = sigf(zg[0]);
    float gf = sigf(zg[1]);
    float gg = fmaxf(zg[2], 0.f);
    float go = sigf(zg[3]);
    float c = gf * c_in[idx] + gi * gg;
    c_out[idx] = c;
    float h = go * fmaxf(c, 0.f);
    h_out[idx] = h;
    __nv_bfloat16 hi = __float2bfloat16(h);
    g_hh[idx] = hi;
    g_hl[idx] = __float2bfloat16(h - __bfloat162float(hi));
}

// -------------------------------------------------------------------------
// Softmax, 3 passes, exp computed once, decoder bias folded in.
// -------------------------------------------------------------------------
__global__ void smax_max_kernel(const float* __restrict__ logits, const float* __restrict__ bd)
{
    __shared__ float red[16];
    const int b = blockIdx.x;
    const float* row = logits + (size_t)b * Vn;
    const int tid = threadIdx.x;
    float m = -1e30f;
    for (int j = tid; j < Vn; j += 512) m = fmaxf(m, row[j] + bd[j]);
    #pragma unroll
    for (int o = 16; o; o >>= 1) m = fmaxf(m, __shfl_xor_sync(0xffffffffu, m, o));
    if ((tid & 31) == 0) red[tid >> 5] = m;
    __syncthreads();
    if (tid < 32) {
        float mm = (tid < 16) ? red[tid] : -1e30f;
        #pragma unroll
        for (int o = 8; o; o >>= 1) mm = fmaxf(mm, __shfl_xor_sync(0xffffffffu, mm, o));
        if (tid == 0) g_rowmax[b] = mm;
    }
}

__global__ void smax_exp_kernel(float* __restrict__ logits, const float* __restrict__ bd)
{
    __shared__ float red[16];
    const int b = blockIdx.x;
    float* row = logits + (size_t)b * Vn;
    const int tid = threadIdx.x;
    const float m = g_rowmax[b];
    float s = 0.f;
    for (int j = tid; j < Vn; j += 512) {
        float e = __expf(row[j] + bd[j] - m);
        row[j] = e;
        s += e;
    }
    #pragma unroll
    for (int o = 16; o; o >>= 1) s += __shfl_xor_sync(0xffffffffu, s, o);
    if ((tid & 31) == 0) red[tid >> 5] = s;
    __syncthreads();
    if (tid < 32) {
        float ss = (tid < 16) ? red[tid] : 0.f;
        #pragma unroll
        for (int o = 8; o; o >>= 1) ss += __shfl_xor_sync(0xffffffffu, ss, o);
        if (tid == 0) g_rowsum[b] = ss;
    }
}

__global__ void smax_scale_kernel(float* __restrict__ logits)
{
    const int b = blockIdx.x;
    float* row = logits + (size_t)b * Vn;
    const float inv = 1.0f / g_rowsum[b];
    for (int j = threadIdx.x; j < Vn; j += 512) row[j] *= inv;
}

// -------------------------------------------------------------------------
// Launch
// -------------------------------------------------------------------------
extern "C" void kernel_launch(void* const* d_in, const int* in_sizes, int n_in,
                              void* d_out, int out_size)
{
    const float* enc     = (const float*)d_in[0];
    const float* word    = (const float*)d_in[1];
    const float* h0      = (const float*)d_in[2];
    const float* c0      = (const float*)d_in[3];
    const int*   speaker = (const int*)  d_in[4];
    const float* persona = (const float*)d_in[6];
    const float* W1 = (const float*)d_in[7];
    const float* U1 = (const float*)d_in[8];
    const float* b1 = (const float*)d_in[9];
    const float* W2 = (const float*)d_in[10];
    const float* U2 = (const float*)d_in[11];
    const float* b2 = (const float*)d_in[12];
    const float* W3 = (const float*)d_in[13];
    const float* U3 = (const float*)d_in[14];
    const float* b3 = (const float*)d_in[15];
    const float* W4 = (const float*)d_in[16];
    const float* U4 = (const float*)d_in[17];
    const float* b4 = (const float*)d_in[18];
    const float* Wd = (const float*)d_in[19];
    const float* bd = (const float*)d_in[20];
    float* out = (float*)d_out;

    static bool attr_done = false;
    if (!attr_done) {
        cudaFuncSetAttribute(gemm_bf3<0>, cudaFuncAttributeMaxDynamicSharedMemorySize, SMEM_TOTAL);
        cudaFuncSetAttribute(gemm_bf3<1>, cudaFuncAttributeMaxDynamicSharedMemorySize, SMEM_TOTAL);
        cudaFuncSetAttribute(gemm_bf3<2>, cudaFuncAttributeMaxDynamicSharedMemorySize, SMEM_TOTAL);
        attr_done = true;
    }

    void *p_a1h, *p_a1l, *p_hh, *p_hl, *p_zp, *p_h, *p_c;
    cudaGetSymbolAddress(&p_a1h, g_a1h);
    cudaGetSymbolAddress(&p_a1l, g_a1l);
    cudaGetSymbolAddress(&p_hh,  g_hh);
    cudaGetSymbolAddress(&p_hl,  g_hl);
    cudaGetSymbolAddress(&p_zp,  g_zp);
    cudaGetSymbolAddress(&p_h,   g_h);
    cudaGetSymbolAddress(&p_c,   g_c);
    __nv_bfloat16* a1h = (__nv_bfloat16*)p_a1h;
    __nv_bfloat16* a1l = (__nv_bfloat16*)p_a1l;
    __nv_bfloat16* hh  = (__nv_bfloat16*)p_hh;
    __nv_bfloat16* hl  = (__nv_bfloat16*)p_hl;
    float* zp = (float*)p_zp;
    float* h  = (float*)p_h;
    float* c  = (float*)p_c;

    float* out_h = out + (size_t)Bn * Vn;
    float* out_c = out_h + (size_t)Bn * Hn;
    const bool has_tail = (out_size >= Bn * Vn + 2 * Bn * Hn);

    // Layer 1 (K=11776, split-K 4, 46 chunks each)
    build_a1_kernel<<<(Bn * KC1 + 255) / 256, 256>>>(enc, word, persona, speaker, h0);
    gemm_bf3<2><<<dim3(G4 / 128, Bn / 128, 4), 512, SMEM_TOTAL>>>(
        a1h, a1l, KC1, W1, U1, G4, zp, G4, KC1 / (BK * 4));
    gates_kernel<<<(Bn * Hn + 255) / 256, 256>>>(zp, b1, 4, c0, h, c);

    // Layers 2..4 (K=512, split-K 4, 2 chunks each)
    const float* Ws[3] = {W2, W3, W4};
    const float* Us[3] = {U2, U3, U4};
    const float* bs[3] = {b2, b3, b4};
    for (int l = 0; l < 3; l++) {
        gemm_bf3<1><<<dim3(G4 / 128, Bn / 128, 4), 512, SMEM_TOTAL>>>(
            hh, hl, Hn, Ws[l], Us[l], G4, zp, G4, Hn / (BK * 4));
        const bool last = (l == 2) && has_tail;
        gates_kernel<<<(Bn * Hn + 255) / 256, 256>>>(zp, bs[l], 4, c,
                                                     last ? out_h : h,
                                                     last ? out_c : c);
    }

    // Decoder (N=32000, K=512, 8 chunks) + softmax (bias folded)
    gemm_bf3<0><<<dim3(Vn / 128, Bn / 128, 1), 512, SMEM_TOTAL>>>(
        hh, hl, Hn, Wd, nullptr, Vn, out, Vn, Hn / BK);
    smax_max_kernel<<<Bn, 512>>>(out, bd);
    smax_exp_kernel<<<Bn, 512>>>(out, bd);
    smax_scale_kernel<<<Bn, 512>>>(out);
}

// round 9
// speedup vs baseline: 3.5565x; 1.0057x over previous
#include <cuda_runtime.h>
#include <cuda_bf16.h>
#include <mma.h>
#include <math.h>
#include <cstdint>

using namespace nvcuda;

// -------------------------------------------------------------------------
// Problem dims
// -------------------------------------------------------------------------
constexpr int Bn = 256, Sn = 20, En = 512, Hn = 512, Vn = 32000;
constexpr int XW  = Sn * En + 2 * En;  // 11264
constexpr int KC1 = XW + Hn;           // 11776 (x | h0)
constexpr int G4  = 4 * Hn;            // 2048
constexpr int BK  = 64;

// -------------------------------------------------------------------------
// Static device scratch
// -------------------------------------------------------------------------
__device__ __align__(16) __nv_bfloat16 g_a1h[Bn * KC1];
__device__ __align__(16) __nv_bfloat16 g_a1l[Bn * KC1];
__device__ __align__(16) __nv_bfloat16 g_hh[Bn * Hn];
__device__ __align__(16) __nv_bfloat16 g_hl[Bn * Hn];
__device__ __align__(16) float g_zp[4 * Bn * G4];   // split-K partials
__device__ __align__(16) float g_h[Bn * Hn];
__device__ __align__(16) float g_c[Bn * Hn];
__device__ float g_rowmax[Bn];
__device__ float g_rowsum[Bn];

// -------------------------------------------------------------------------
// Helpers
// -------------------------------------------------------------------------
__device__ __forceinline__ uint32_t smem_u32(const void* p) {
    uint32_t a;
    asm("{ .reg .u64 t; cvta.to.shared.u64 t, %1; cvt.u32.u64 %0, t; }" : "=r"(a) : "l"(p));
    return a;
}
__device__ __forceinline__ void cp16(uint32_t s, const void* g) {
    asm volatile("cp.async.cg.shared.global [%0], [%1], 16;" :: "r"(s), "l"(g));
}
#define CP_COMMIT() asm volatile("cp.async.commit_group;" ::: "memory")
#define CP_WAIT1()  asm volatile("cp.async.wait_group 1;" ::: "memory")

__device__ __forceinline__ uint32_t pack_bf2f(float a, float b) {
    __nv_bfloat162 t = __floats2bfloat162_rn(a, b);
    return *reinterpret_cast<uint32_t*>(&t);
}
__device__ __forceinline__ void split_f(float v, float& hi, float& lo) {
    __nv_bfloat16 h = __float2bfloat16(v);
    hi = __bfloat162float(h);
    lo = v - hi;
}

// -------------------------------------------------------------------------
// SMEM layout: A 3 slots x {hi,lo} 128x(64 pad 72) bf16,
//              B 2 bufs  x {hi,lo} 64x(128 pad 136) bf16
// -------------------------------------------------------------------------
constexpr int A_PITCH = 72;                       // elems; row = 144 B
constexpr int A_ARR   = 128 * A_PITCH * 2;        // 18432 B
constexpr int A_SLOT  = 2 * A_ARR;                // 36864 B
constexpr int OFF_B   = 3 * A_SLOT;               // 110592
constexpr int B_PITCH = 136;                      // elems; row = 272 B
constexpr int B_ARR   = 64 * B_PITCH * 2;         // 17408 B
constexpr int B_BUF   = 2 * B_ARR;                // 34816 B
constexpr int SMEM_TOTAL = OFF_B + 2 * B_BUF;     // 180224 B

// -------------------------------------------------------------------------
// GEMM: C[M,N] = A @ B; A = (Ah+Al) bf16 row-major; B fp32 [K][N].
// 3-term split-bf16 (hi*hi + hi*lo + lo*hi), term-outermost issue order so
// consecutive HMMAs on the same accumulator are 4 issues apart.
// 512 threads, warp tile 32x32.
// BMODE: 0 = B1; 1 = B1+B2 elementwise; 2 = rows<XW from B1 else B2.
// split-K via blockIdx.z into partial buffers.
// -------------------------------------------------------------------------
template<int BMODE>
__global__ void __launch_bounds__(512)
gemm_bf3(const __nv_bfloat16* __restrict__ Ah, const __nv_bfloat16* __restrict__ Al,
         int lda,
         const float* __restrict__ B1, const float* __restrict__ B2, int ldb,
         float* __restrict__ C, int ldc, int chunks)
{
    extern __shared__ __align__(16) char smem[];
    const uint32_t sbase = smem_u32(smem);

    const int tid = threadIdx.x;
    const int wid = tid >> 5;
    const int m0 = blockIdx.y * 128;
    const int n0 = blockIdx.x * 128;
    const int kbase = blockIdx.z * chunks * BK;
    C += (size_t)blockIdx.z * (size_t)(gridDim.y * 128) * ldc;

    // A: rows {tid>>3, tid>>3 + 64}, granule tid&7 (8 x 16B per 128B row)
    const int a_row = tid >> 3;          // 0..63
    const int a_g   = tid & 7;           // 0..7
    // B: 4 float4 per thread. 64 rows x 32 float4
    const int b_r = tid >> 5;            // +i*16
    const int b_c = (tid & 31) << 2;

    auto issueA = [&](int c, int slot) {
        const int k0 = kbase + c * BK;
        #pragma unroll
        for (int i = 0; i < 2; i++) {
            const int row = a_row + i * 64;
            const size_t goff = (size_t)(m0 + row) * lda + k0 + a_g * 8;
            const uint32_t soff = sbase + slot * A_SLOT + row * 144 + a_g * 16;
            cp16(soff,         Ah + goff);
            cp16(soff + A_ARR, Al + goff);
        }
    };

    float4 rB[4], rB2[4];
    auto loadB = [&](int c) {
        const int k0 = kbase + c * BK;
        const float* bp;
        if (BMODE == 2)
            bp = (k0 < XW) ? (B1 + (size_t)k0 * ldb) : (B2 + (size_t)(k0 - XW) * ldb);
        else
            bp = B1 + (size_t)k0 * ldb;
        #pragma unroll
        for (int i = 0; i < 4; i++) {
            const size_t off = (size_t)(b_r + i * 16) * ldb + n0 + b_c;
            rB[i] = *reinterpret_cast<const float4*>(bp + off);
            if (BMODE == 1)
                rB2[i] = *reinterpret_cast<const float4*>(B2 + (size_t)(k0 + b_r + i * 16) * ldb + n0 + b_c);
        }
    };
    auto storeB = [&](int buf) {
        char* bb = smem + OFF_B + buf * B_BUF;
        #pragma unroll
        for (int i = 0; i < 4; i++) {
            float x0 = rB[i].x, x1 = rB[i].y, x2 = rB[i].z, x3 = rB[i].w;
            if (BMODE == 1) { x0 += rB2[i].x; x1 += rB2[i].y; x2 += rB2[i].z; x3 += rB2[i].w; }
            float h0, l0, h1, l1, h2, l2, h3, l3;
            split_f(x0, h0, l0); split_f(x1, h1, l1);
            split_f(x2, h2, l2); split_f(x3, h3, l3);
            const int off = (b_r + i * 16) * 272 + b_c * 2;   // bytes
            uint2 hv, lv;
            hv.x = pack_bf2f(h0, h1); hv.y = pack_bf2f(h2, h3);
            lv.x = pack_bf2f(l0, l1); lv.y = pack_bf2f(l2, l3);
            *reinterpret_cast<uint2*>(bb + off)         = hv;
            *reinterpret_cast<uint2*>(bb + B_ARR + off) = lv;
        }
    };

    wmma::fragment<wmma::accumulator, 16, 16, 16, float> acc[2][2];
    #pragma unroll
    for (int i = 0; i < 2; i++)
        #pragma unroll
        for (int j = 0; j < 2; j++)
            wmma::fill_fragment(acc[i][j], 0.0f);

    const int wm = (wid & 3) * 32;
    const int wn = (wid >> 2) * 32;

    // Prologue
    issueA(0, 0); CP_COMMIT();
    if (chunks > 1) issueA(1, 1);
    CP_COMMIT();
    loadB(0);
    storeB(0);

    for (int c = 0; c < chunks; c++) {
        CP_WAIT1();            // A(c) landed (A(c+1) may be in flight)
        __syncthreads();

        if (c + 2 < chunks) issueA(c + 2, (c + 2) % 3);
        CP_COMMIT();
        if (c + 1 < chunks) loadB(c + 1);

        const __nv_bfloat16* sAh = (const __nv_bfloat16*)(smem + (c % 3) * A_SLOT);
        const __nv_bfloat16* sAl = (const __nv_bfloat16*)(smem + (c % 3) * A_SLOT + A_ARR);
        const __nv_bfloat16* sBh = (const __nv_bfloat16*)(smem + OFF_B + (c & 1) * B_BUF);
        const __nv_bfloat16* sBl = (const __nv_bfloat16*)(smem + OFF_B + (c & 1) * B_BUF + B_ARR);
        #pragma unroll
        for (int kk = 0; kk < 4; kk++) {
            wmma::fragment<wmma::matrix_a, 16, 16, 16, __nv_bfloat16, wmma::row_major> fah[2], fal[2];
            wmma::fragment<wmma::matrix_b, 16, 16, 16, __nv_bfloat16, wmma::row_major> fbh[2], fbl[2];
            #pragma unroll
            for (int i = 0; i < 2; i++) {
                wmma::load_matrix_sync(fah[i], sAh + (wm + i * 16) * A_PITCH + kk * 16, A_PITCH);
                wmma::load_matrix_sync(fal[i], sAl + (wm + i * 16) * A_PITCH + kk * 16, A_PITCH);
            }
            #pragma unroll
            for (int j = 0; j < 2; j++) {
                wmma::load_matrix_sync(fbh[j], sBh + (kk * 16) * B_PITCH + wn + j * 16, B_PITCH);
                wmma::load_matrix_sync(fbl[j], sBl + (kk * 16) * B_PITCH + wn + j * 16, B_PITCH);
            }
            // term-outermost: consecutive mmas on a given acc are 4 issues apart
            #pragma unroll
            for (int i = 0; i < 2; i++)
                #pragma unroll
                for (int j = 0; j < 2; j++)
                    wmma::mma_sync(acc[i][j], fah[i], fbh[j], acc[i][j]);
            #pragma unroll
            for (int i = 0; i < 2; i++)
                #pragma unroll
                for (int j = 0; j < 2; j++)
                    wmma::mma_sync(acc[i][j], fah[i], fbl[j], acc[i][j]);
            #pragma unroll
            for (int i = 0; i < 2; i++)
                #pragma unroll
                for (int j = 0; j < 2; j++)
                    wmma::mma_sync(acc[i][j], fal[i], fbh[j], acc[i][j]);
        }

        if (c + 1 < chunks) storeB((c + 1) & 1);
    }

    // Epilogue: direct stores (bias folded downstream)
    #pragma unroll
    for (int i = 0; i < 2; i++)
        #pragma unroll
        for (int j = 0; j < 2; j++) {
            float* cp = C + (size_t)(m0 + wm + i * 16) * ldc + n0 + wn + j * 16;
            wmma::store_matrix_sync(cp, acc[i][j], ldc, wmma::mem_row_major);
        }
}

// -------------------------------------------------------------------------
// Build split-bf16 A for layer 1
// -------------------------------------------------------------------------
__global__ void build_a1_kernel(const float* __restrict__ enc, const float* __restrict__ word,
                                const float* __restrict__ persona, const int* __restrict__ speaker,
                                const float* __restrict__ h0)
{
    int idx = blockIdx.x * blockDim.x + threadIdx.x;
    if (idx >= Bn * KC1) return;
    int b = idx / KC1, k = idx - b * KC1;
    float v;
    if (k < Sn * En)           v = enc[(size_t)b * Sn * En + k];
    else if (k < Sn * En + En) v = word[b * En + k - Sn * En];
    else if (k < XW)           v = persona[(size_t)speaker[b] * En + k - (Sn * En + En)];
    else                       v = h0[b * Hn + k - XW];
    __nv_bfloat16 hi = __float2bfloat16(v);
    g_a1h[idx] = hi;
    g_a1l[idx] = __float2bfloat16(v - __bfloat162float(hi));
}

// -------------------------------------------------------------------------
// Gates: reduce split-K partials + bias, LSTM cell, emit h (fp32 + hi/lo)
// -------------------------------------------------------------------------
__device__ __forceinline__ float sigf(float x) { return 1.0f / (1.0f + __expf(-x)); }

__global__ void gates_kernel(const float* __restrict__ zp, const float* __restrict__ bias,
                             int nsplit, const float* __restrict__ c_in,
                             float* __restrict__ h_out, float* __restrict__ c_out)
{
    int idx = blockIdx.x * blockDim.x + threadIdx.x;
    if (idx >= Bn * Hn) return;
    int b = idx >> 9, j = idx & (Hn - 1);
    float zg[4];
    #pragma unroll
    for (int g = 0; g < 4; g++) {
        float s = bias[g * Hn + j];
        for (int sp = 0; sp < nsplit; sp++)
            s += zp[(size_t)sp * Bn * G4 + (size_t)b * G4 + g * Hn + j];
        zg[g] = s;
    }
    float gi = sigf(zg[0]);
    float gf = sigf(zg[1]);
    float gg = fmaxf(zg[2], 0.f);
    float go = sigf(zg[3]);
    float c = gf * c_in[idx] + gi * gg;
    c_out[idx] = c;
    float h = go * fmaxf(c, 0.f);
    h_out[idx] = h;
    __nv_bfloat16 hi = __float2bfloat16(h);
    g_hh[idx] = hi;
    g_hl[idx] = __float2bfloat16(h - __bfloat162float(hi));
}

// -------------------------------------------------------------------------
// Softmax, 3 passes, exp computed once, decoder bias folded in.
// -------------------------------------------------------------------------
__global__ void smax_max_kernel(const float* __restrict__ logits, const float* __restrict__ bd)
{
    __shared__ float red[16];
    const int b = blockIdx.x;
    const float* row = logits + (size_t)b * Vn;
    const int tid = threadIdx.x;
    float m = -1e30f;
    for (int j = tid; j < Vn; j += 512) m = fmaxf(m, row[j] + bd[j]);
    #pragma unroll
    for (int o = 16; o; o >>= 1) m = fmaxf(m, __shfl_xor_sync(0xffffffffu, m, o));
    if ((tid & 31) == 0) red[tid >> 5] = m;
    __syncthreads();
    if (tid < 32) {
        float mm = (tid < 16) ? red[tid] : -1e30f;
        #pragma unroll
        for (int o = 8; o; o >>= 1) mm = fmaxf(mm, __shfl_xor_sync(0xffffffffu, mm, o));
        if (tid == 0) g_rowmax[b] = mm;
    }
}

__global__ void smax_exp_kernel(float* __restrict__ logits, const float* __restrict__ bd)
{
    __shared__ float red[16];
    const int b = blockIdx.x;
    float* row = logits + (size_t)b * Vn;
    const int tid = threadIdx.x;
    const float m = g_rowmax[b];
    float s = 0.f;
    for (int j = tid; j < Vn; j += 512) {
        float e = __expf(row[j] + bd[j] - m);
        row[j] = e;
        s += e;
    }
    #pragma unroll
    for (int o = 16; o; o >>= 1) s += __shfl_xor_sync(0xffffffffu, s, o);
    if ((tid & 31) == 0) red[tid >> 5] = s;
    __syncthreads();
    if (tid < 32) {
        float ss = (tid < 16) ? red[tid] : 0.f;
        #pragma unroll
        for (int o = 8; o; o >>= 1) ss += __shfl_xor_sync(0xffffffffu, ss, o);
        if (tid == 0) g_rowsum[b] = ss;
    }
}

__global__ void smax_scale_kernel(float* __restrict__ logits)
{
    const int b = blockIdx.x;
    float* row = logits + (size_t)b * Vn;
    const float inv = 1.0f / g_rowsum[b];
    for (int j = threadIdx.x; j < Vn; j += 512) row[j] *= inv;
}

// -------------------------------------------------------------------------
// Launch
// -------------------------------------------------------------------------
extern "C" void kernel_launch(void* const* d_in, const int* in_sizes, int n_in,
                              void* d_out, int out_size)
{
    const float* enc     = (const float*)d_in[0];
    const float* word    = (const float*)d_in[1];
    const float* h0      = (const float*)d_in[2];
    const float* c0      = (const float*)d_in[3];
    const int*   speaker = (const int*)  d_in[4];
    const float* persona = (const float*)d_in[6];
    const float* W1 = (const float*)d_in[7];
    const float* U1 = (const float*)d_in[8];
    const float* b1 = (const float*)d_in[9];
    const float* W2 = (const float*)d_in[10];
    const float* U2 = (const float*)d_in[11];
    const float* b2 = (const float*)d_in[12];
    const float* W3 = (const float*)d_in[13];
    const float* U3 = (const float*)d_in[14];
    const float* b3 = (const float*)d_in[15];
    const float* W4 = (const float*)d_in[16];
    const float* U4 = (const float*)d_in[17];
    const float* b4 = (const float*)d_in[18];
    const float* Wd = (const float*)d_in[19];
    const float* bd = (const float*)d_in[20];
    float* out = (float*)d_out;

    static bool attr_done = false;
    if (!attr_done) {
        cudaFuncSetAttribute(gemm_bf3<0>, cudaFuncAttributeMaxDynamicSharedMemorySize, SMEM_TOTAL);
        cudaFuncSetAttribute(gemm_bf3<1>, cudaFuncAttributeMaxDynamicSharedMemorySize, SMEM_TOTAL);
        cudaFuncSetAttribute(gemm_bf3<2>, cudaFuncAttributeMaxDynamicSharedMemorySize, SMEM_TOTAL);
        attr_done = true;
    }

    void *p_a1h, *p_a1l, *p_hh, *p_hl, *p_zp, *p_h, *p_c;
    cudaGetSymbolAddress(&p_a1h, g_a1h);
    cudaGetSymbolAddress(&p_a1l, g_a1l);
    cudaGetSymbolAddress(&p_hh,  g_hh);
    cudaGetSymbolAddress(&p_hl,  g_hl);
    cudaGetSymbolAddress(&p_zp,  g_zp);
    cudaGetSymbolAddress(&p_h,   g_h);
    cudaGetSymbolAddress(&p_c,   g_c);
    __nv_bfloat16* a1h = (__nv_bfloat16*)p_a1h;
    __nv_bfloat16* a1l = (__nv_bfloat16*)p_a1l;
    __nv_bfloat16* hh  = (__nv_bfloat16*)p_hh;
    __nv_bfloat16* hl  = (__nv_bfloat16*)p_hl;
    float* zp = (float*)p_zp;
    float* h  = (float*)p_h;
    float* c  = (float*)p_c;

    float* out_h = out + (size_t)Bn * Vn;
    float* out_c = out_h + (size_t)Bn * Hn;
    const bool has_tail = (out_size >= Bn * Vn + 2 * Bn * Hn);

    // Layer 1 (K=11776, split-K 4, 46 chunks each)
    build_a1_kernel<<<(Bn * KC1 + 255) / 256, 256>>>(enc, word, persona, speaker, h0);
    gemm_bf3<2><<<dim3(G4 / 128, Bn / 128, 4), 512, SMEM_TOTAL>>>(
        a1h, a1l, KC1, W1, U1, G4, zp, G4, KC1 / (BK * 4));
    gates_kernel<<<(Bn * Hn + 255) / 256, 256>>>(zp, b1, 4, c0, h, c);

    // Layers 2..4 (K=512, split-K 4, 2 chunks each)
    const float* Ws[3] = {W2, W3, W4};
    const float* Us[3] = {U2, U3, U4};
    const float* bs[3] = {b2, b3, b4};
    for (int l = 0; l < 3; l++) {
        gemm_bf3<1><<<dim3(G4 / 128, Bn / 128, 4), 512, SMEM_TOTAL>>>(
            hh, hl, Hn, Ws[l], Us[l], G4, zp, G4, Hn / (BK * 4));
        const bool last = (l == 2) && has_tail;
        gates_kernel<<<(Bn * Hn + 255) / 256, 256>>>(zp, bs[l], 4, c,
                                                     last ? out_h : h,
                                                     last ? out_c : c);
    }

    // Decoder (N=32000, K=512, 8 chunks) + softmax (bias folded)
    gemm_bf3<0><<<dim3(Vn / 128, Bn / 128, 1), 512, SMEM_TOTAL>>>(
        hh, hl, Hn, Wd, nullptr, Vn, out, Vn, Hn / BK);
    smax_max_kernel<<<Bn, 512>>>(out, bd);
    smax_exp_kernel<<<Bn, 512>>>(out, bd);
    smax_scale_kernel<<<Bn, 512>>>(out);
}

// round 10
// speedup vs baseline: 3.7663x; 1.0590x over previous
#include <cuda_runtime.h>
#include <cuda_bf16.h>
#include <mma.h>
#include <math.h>
#include <cstdint>

using namespace nvcuda;

// -------------------------------------------------------------------------
// Problem dims
// -------------------------------------------------------------------------
constexpr int Bn = 256, Sn = 20, En = 512, Hn = 512, Vn = 32000;
constexpr int XW  = Sn * En + 2 * En;  // 11264
constexpr int KC1 = XW + Hn;           // 11776 (x | h0)
constexpr int G4  = 4 * Hn;            // 2048
constexpr int BK  = 32;

// -------------------------------------------------------------------------
// Static device scratch
// -------------------------------------------------------------------------
__device__ __align__(16) __nv_bfloat16 g_a1h[Bn * KC1];
__device__ __align__(16) __nv_bfloat16 g_a1l[Bn * KC1];
__device__ __align__(16) __nv_bfloat16 g_hh[Bn * Hn];
__device__ __align__(16) __nv_bfloat16 g_hl[Bn * Hn];
__device__ __align__(16) float g_zp[8 * Bn * G4];   // split-K partials
__device__ __align__(16) float g_h[Bn * Hn];
__device__ __align__(16) float g_c[Bn * Hn];
__device__ float g_rowmax[Bn];
__device__ float g_rowsum[Bn];

// -------------------------------------------------------------------------
// Helpers
// -------------------------------------------------------------------------
__device__ __forceinline__ uint32_t smem_u32(const void* p) {
    uint32_t a;
    asm("{ .reg .u64 t; cvta.to.shared.u64 t, %1; cvt.u32.u64 %0, t; }" : "=r"(a) : "l"(p));
    return a;
}
__device__ __forceinline__ void cp16(uint32_t s, const void* g) {
    asm volatile("cp.async.cg.shared.global [%0], [%1], 16;" :: "r"(s), "l"(g));
}
#define CP_COMMIT() asm volatile("cp.async.commit_group;" ::: "memory")
#define CP_WAIT1()  asm volatile("cp.async.wait_group 1;" ::: "memory")

__device__ __forceinline__ uint32_t pack_bf2f(float a, float b) {
    __nv_bfloat162 t = __floats2bfloat162_rn(a, b);
    return *reinterpret_cast<uint32_t*>(&t);
}
__device__ __forceinline__ void split_f(float v, float& hi, float& lo) {
    __nv_bfloat16 h = __float2bfloat16(v);
    hi = __bfloat162float(h);
    lo = v - hi;
}

// -------------------------------------------------------------------------
// SMEM layout (per CTA, 96256 B total -> 2 CTAs/SM):
//   A: 3 slots x {hi,lo} 128 x (32 pad 40) bf16   (20480 B / slot)
//   B: 2 bufs  x {hi,lo} 32 x (128 pad 136) bf16  (17408 B / buf)
// -------------------------------------------------------------------------
constexpr int A_PITCH = 40;                       // elems; row = 80 B
constexpr int A_ARR   = 128 * A_PITCH * 2;        // 10240 B
constexpr int A_SLOT  = 2 * A_ARR;                // 20480 B
constexpr int OFF_B   = 3 * A_SLOT;               // 61440
constexpr int B_PITCH = 136;                      // elems; row = 272 B
constexpr int B_ARR   = 32 * B_PITCH * 2;         // 8704 B
constexpr int B_BUF   = 2 * B_ARR;                // 17408 B
constexpr int SMEM_TOTAL = OFF_B + 2 * B_BUF;     // 96256 B

// -------------------------------------------------------------------------
// GEMM: C[M,N] = A @ B; A = (Ah+Al) bf16 row-major; B fp32 [K][N].
// 3-term split-bf16 (hi*hi + hi*lo + lo*hi). 256 threads, 8 warps of 32x64.
// BMODE: 0 = B1; 1 = B1+B2 elementwise; 2 = rows<XW from B1 else B2.
// split-K via blockIdx.z into partial buffers.
// -------------------------------------------------------------------------
template<int BMODE>
__global__ void __launch_bounds__(256, 2)
gemm_bf3(const __nv_bfloat16* __restrict__ Ah, const __nv_bfloat16* __restrict__ Al,
         int lda,
         const float* __restrict__ B1, const float* __restrict__ B2, int ldb,
         float* __restrict__ C, int ldc, int chunks)
{
    extern __shared__ __align__(16) char smem[];
    const uint32_t sbase = smem_u32(smem);

    const int tid = threadIdx.x;
    const int wid = tid >> 5;
    const int m0 = blockIdx.y * 128;
    const int n0 = blockIdx.x * 128;
    const int kbase = blockIdx.z * chunks * BK;
    C += (size_t)blockIdx.z * (size_t)(gridDim.y * 128) * ldc;

    // B: 4 float4 per thread (32 rows x 32 float4)
    const int b_r = tid >> 5;            // +i*8
    const int b_c = (tid & 31) << 2;

    auto issueA = [&](int c, int slot) {
        const int k0 = kbase + c * BK;
        #pragma unroll
        for (int i = 0; i < 2; i++) {
            const int t2 = tid + i * 256;          // 0..511
            const int row = t2 >> 2;               // 0..127
            const int g   = t2 & 3;                // 16B granule within 64B row
            const size_t goff = (size_t)(m0 + row) * lda + k0 + g * 8;
            const uint32_t soff = sbase + slot * A_SLOT + row * 80 + g * 16;
            cp16(soff,         Ah + goff);
            cp16(soff + A_ARR, Al + goff);
        }
    };

    float4 rB[4], rB2[4];
    auto loadB = [&](int c) {
        const int k0 = kbase + c * BK;
        const float* bp;
        if (BMODE == 2)
            bp = (k0 < XW) ? (B1 + (size_t)k0 * ldb) : (B2 + (size_t)(k0 - XW) * ldb);
        else
            bp = B1 + (size_t)k0 * ldb;
        #pragma unroll
        for (int i = 0; i < 4; i++) {
            const size_t off = (size_t)(b_r + i * 8) * ldb + n0 + b_c;
            rB[i] = *reinterpret_cast<const float4*>(bp + off);
            if (BMODE == 1)
                rB2[i] = *reinterpret_cast<const float4*>(B2 + (size_t)(k0 + b_r + i * 8) * ldb + n0 + b_c);
        }
    };
    auto storeB = [&](int buf) {
        char* bb = smem + OFF_B + buf * B_BUF;
        #pragma unroll
        for (int i = 0; i < 4; i++) {
            float x0 = rB[i].x, x1 = rB[i].y, x2 = rB[i].z, x3 = rB[i].w;
            if (BMODE == 1) { x0 += rB2[i].x; x1 += rB2[i].y; x2 += rB2[i].z; x3 += rB2[i].w; }
            float h0, l0, h1, l1, h2, l2, h3, l3;
            split_f(x0, h0, l0); split_f(x1, h1, l1);
            split_f(x2, h2, l2); split_f(x3, h3, l3);
            const int off = (b_r + i * 8) * 272 + b_c * 2;   // bytes
            uint2 hv, lv;
            hv.x = pack_bf2f(h0, h1); hv.y = pack_bf2f(h2, h3);
            lv.x = pack_bf2f(l0, l1); lv.y = pack_bf2f(l2, l3);
            *reinterpret_cast<uint2*>(bb + off)         = hv;
            *reinterpret_cast<uint2*>(bb + B_ARR + off) = lv;
        }
    };

    // warp tile 32x64: warps 4 (M) x 2 (N)
    wmma::fragment<wmma::accumulator, 16, 16, 16, float> acc[2][4];
    #pragma unroll
    for (int i = 0; i < 2; i++)
        #pragma unroll
        for (int j = 0; j < 4; j++)
            wmma::fill_fragment(acc[i][j], 0.0f);

    const int wm = (wid & 3) * 32;
    const int wn = (wid >> 2) * 64;

    // Prologue
    issueA(0, 0); CP_COMMIT();
    if (chunks > 1) issueA(1, 1);
    CP_COMMIT();
    loadB(0);
    storeB(0);

    for (int c = 0; c < chunks; c++) {
        CP_WAIT1();            // A(c) landed (A(c+1) may be in flight)
        __syncthreads();

        if (c + 2 < chunks) issueA(c + 2, (c + 2) % 3);
        CP_COMMIT();
        if (c + 1 < chunks) loadB(c + 1);

        const __nv_bfloat16* sAh = (const __nv_bfloat16*)(smem + (c % 3) * A_SLOT);
        const __nv_bfloat16* sAl = (const __nv_bfloat16*)(smem + (c % 3) * A_SLOT + A_ARR);
        const __nv_bfloat16* sBh = (const __nv_bfloat16*)(smem + OFF_B + (c & 1) * B_BUF);
        const __nv_bfloat16* sBl = (const __nv_bfloat16*)(smem + OFF_B + (c & 1) * B_BUF + B_ARR);
        #pragma unroll
        for (int kk = 0; kk < 2; kk++) {
            wmma::fragment<wmma::matrix_a, 16, 16, 16, __nv_bfloat16, wmma::row_major> fah[2], fal[2];
            #pragma unroll
            for (int i = 0; i < 2; i++) {
                wmma::load_matrix_sync(fah[i], sAh + (wm + i * 16) * A_PITCH + kk * 16, A_PITCH);
                wmma::load_matrix_sync(fal[i], sAl + (wm + i * 16) * A_PITCH + kk * 16, A_PITCH);
            }
            #pragma unroll
            for (int j = 0; j < 4; j++) {
                wmma::fragment<wmma::matrix_b, 16, 16, 16, __nv_bfloat16, wmma::row_major> fbh, fbl;
                wmma::load_matrix_sync(fbh, sBh + (kk * 16) * B_PITCH + wn + j * 16, B_PITCH);
                wmma::load_matrix_sync(fbl, sBl + (kk * 16) * B_PITCH + wn + j * 16, B_PITCH);
                #pragma unroll
                for (int i = 0; i < 2; i++)
                    wmma::mma_sync(acc[i][j], fah[i], fbh, acc[i][j]);
                #pragma unroll
                for (int i = 0; i < 2; i++)
                    wmma::mma_sync(acc[i][j], fah[i], fbl, acc[i][j]);
                #pragma unroll
                for (int i = 0; i < 2; i++)
                    wmma::mma_sync(acc[i][j], fal[i], fbh, acc[i][j]);
            }
        }

        if (c + 1 < chunks) storeB((c + 1) & 1);
    }

    // Epilogue: direct stores (bias folded downstream)
    #pragma unroll
    for (int i = 0; i < 2; i++)
        #pragma unroll
        for (int j = 0; j < 4; j++) {
            float* cp = C + (size_t)(m0 + wm + i * 16) * ldc + n0 + wn + j * 16;
            wmma::store_matrix_sync(cp, acc[i][j], ldc, wmma::mem_row_major);
        }
}

// -------------------------------------------------------------------------
// Build split-bf16 A for layer 1
// -------------------------------------------------------------------------
__global__ void build_a1_kernel(const float* __restrict__ enc, const float* __restrict__ word,
                                const float* __restrict__ persona, const int* __restrict__ speaker,
                                const float* __restrict__ h0)
{
    int idx = blockIdx.x * blockDim.x + threadIdx.x;
    if (idx >= Bn * KC1) return;
    int b = idx / KC1, k = idx - b * KC1;
    float v;
    if (k < Sn * En)           v = enc[(size_t)b * Sn * En + k];
    else if (k < Sn * En + En) v = word[b * En + k - Sn * En];
    else if (k < XW)           v = persona[(size_t)speaker[b] * En + k - (Sn * En + En)];
    else                       v = h0[b * Hn + k - XW];
    __nv_bfloat16 hi = __float2bfloat16(v);
    g_a1h[idx] = hi;
    g_a1l[idx] = __float2bfloat16(v - __bfloat162float(hi));
}

// -------------------------------------------------------------------------
// Gates: reduce split-K partials + bias, LSTM cell, emit h (fp32 + hi/lo)
// -------------------------------------------------------------------------
__device__ __forceinline__ float sigf(float x) { return 1.0f / (1.0f + __expf(-x)); }

__global__ void gates_kernel(const float* __restrict__ zp, const float* __restrict__ bias,
                             int nsplit, const float* __restrict__ c_in,
                             float* __restrict__ h_out, float* __restrict__ c_out)
{
    int idx = blockIdx.x * blockDim.x + threadIdx.x;
    if (idx >= Bn * Hn) return;
    int b = idx >> 9, j = idx & (Hn - 1);
    float zg[4];
    #pragma unroll
    for (int g = 0; g < 4; g++) {
        float s = bias[g * Hn + j];
        for (int sp = 0; sp < nsplit; sp++)
            s += zp[(size_t)sp * Bn * G4 + (size_t)b * G4 + g * Hn + j];
        zg[g] = s;
    }
    float gi = sigf(zg[0]);
    float gf = sigf(zg[1]);
    float gg = fmaxf(zg[2], 0.f);
    float go = sigf(zg[3]);
    float c = gf * c_in[idx] + gi * gg;
    c_out[idx] = c;
    float h = go * fmaxf(c, 0.f);
    h_out[idx] = h;
    __nv_bfloat16 hi = __float2bfloat16(h);
    g_hh[idx] = hi;
    g_hl[idx] = __float2bfloat16(h - __bfloat162float(hi));
}

// -------------------------------------------------------------------------
// Softmax, 3 passes, exp computed once, decoder bias folded in.
// -------------------------------------------------------------------------
__global__ void smax_max_kernel(const float* __restrict__ logits, const float* __restrict__ bd)
{
    __shared__ float red[16];
    const int b = blockIdx.x;
    const float* row = logits + (size_t)b * Vn;
    const int tid = threadIdx.x;
    float m = -1e30f;
    for (int j = tid; j < Vn; j += 512) m = fmaxf(m, row[j] + bd[j]);
    #pragma unroll
    for (int o = 16; o; o >>= 1) m = fmaxf(m, __shfl_xor_sync(0xffffffffu, m, o));
    if ((tid & 31) == 0) red[tid >> 5] = m;
    __syncthreads();
    if (tid < 32) {
        float mm = (tid < 16) ? red[tid] : -1e30f;
        #pragma unroll
        for (int o = 8; o; o >>= 1) mm = fmaxf(mm, __shfl_xor_sync(0xffffffffu, mm, o));
        if (tid == 0) g_rowmax[b] = mm;
    }
}

__global__ void smax_exp_kernel(float* __restrict__ logits, const float* __restrict__ bd)
{
    __shared__ float red[16];
    const int b = blockIdx.x;
    float* row = logits + (size_t)b * Vn;
    const int tid = threadIdx.x;
    const float m = g_rowmax[b];
    float s = 0.f;
    for (int j = tid; j < Vn; j += 512) {
        float e = __expf(row[j] + bd[j] - m);
        row[j] = e;
        s += e;
    }
    #pragma unroll
    for (int o = 16; o; o >>= 1) s += __shfl_xor_sync(0xffffffffu, s, o);
    if ((tid & 31) == 0) red[tid >> 5] = s;
    __syncthreads();
    if (tid < 32) {
        float ss = (tid < 16) ? red[tid] : 0.f;
        #pragma unroll
        for (int o = 8; o; o >>= 1) ss += __shfl_xor_sync(0xffffffffu, ss, o);
        if (tid == 0) g_rowsum[b] = ss;
    }
}

__global__ void smax_scale_kernel(float* __restrict__ logits)
{
    const int b = blockIdx.x;
    float* row = logits + (size_t)b * Vn;
    const float inv = 1.0f / g_rowsum[b];
    for (int j = threadIdx.x; j < Vn; j += 512) row[j] *= inv;
}

// -------------------------------------------------------------------------
// Launch
// -------------------------------------------------------------------------
extern "C" void kernel_launch(void* const* d_in, const int* in_sizes, int n_in,
                              void* d_out, int out_size)
{
    const float* enc     = (const float*)d_in[0];
    const float* word    = (const float*)d_in[1];
    const float* h0      = (const float*)d_in[2];
    const float* c0      = (const float*)d_in[3];
    const int*   speaker = (const int*)  d_in[4];
    const float* persona = (const float*)d_in[6];
    const float* W1 = (const float*)d_in[7];
    const float* U1 = (const float*)d_in[8];
    const float* b1 = (const float*)d_in[9];
    const float* W2 = (const float*)d_in[10];
    const float* U2 = (const float*)d_in[11];
    const float* b2 = (const float*)d_in[12];
    const float* W3 = (const float*)d_in[13];
    const float* U3 = (const float*)d_in[14];
    const float* b3 = (const float*)d_in[15];
    const float* W4 = (const float*)d_in[16];
    const float* U4 = (const float*)d_in[17];
    const float* b4 = (const float*)d_in[18];
    const float* Wd = (const float*)d_in[19];
    const float* bd = (const float*)d_in[20];
    float* out = (float*)d_out;

    static bool attr_done = false;
    if (!attr_done) {
        cudaFuncSetAttribute(gemm_bf3<0>, cudaFuncAttributeMaxDynamicSharedMemorySize, SMEM_TOTAL);
        cudaFuncSetAttribute(gemm_bf3<1>, cudaFuncAttributeMaxDynamicSharedMemorySize, SMEM_TOTAL);
        cudaFuncSetAttribute(gemm_bf3<2>, cudaFuncAttributeMaxDynamicSharedMemorySize, SMEM_TOTAL);
        attr_done = true;
    }

    void *p_a1h, *p_a1l, *p_hh, *p_hl, *p_zp, *p_h, *p_c;
    cudaGetSymbolAddress(&p_a1h, g_a1h);
    cudaGetSymbolAddress(&p_a1l, g_a1l);
    cudaGetSymbolAddress(&p_hh,  g_hh);
    cudaGetSymbolAddress(&p_hl,  g_hl);
    cudaGetSymbolAddress(&p_zp,  g_zp);
    cudaGetSymbolAddress(&p_h,   g_h);
    cudaGetSymbolAddress(&p_c,   g_c);
    __nv_bfloat16* a1h = (__nv_bfloat16*)p_a1h;
    __nv_bfloat16* a1l = (__nv_bfloat16*)p_a1l;
    __nv_bfloat16* hh  = (__nv_bfloat16*)p_hh;
    __nv_bfloat16* hl  = (__nv_bfloat16*)p_hl;
    float* zp = (float*)p_zp;
    float* h  = (float*)p_h;
    float* c  = (float*)p_c;

    float* out_h = out + (size_t)Bn * Vn;
    float* out_c = out_h + (size_t)Bn * Hn;
    const bool has_tail = (out_size >= Bn * Vn + 2 * Bn * Hn);

    // Layer 1 (K=11776, split-K 8, 46 BK32 chunks each; 256 CTAs, one wave)
    build_a1_kernel<<<(Bn * KC1 + 255) / 256, 256>>>(enc, word, persona, speaker, h0);
    gemm_bf3<2><<<dim3(G4 / 128, Bn / 128, 8), 256, SMEM_TOTAL>>>(
        a1h, a1l, KC1, W1, U1, G4, zp, G4, KC1 / (BK * 8));
    gates_kernel<<<(Bn * Hn + 255) / 256, 256>>>(zp, b1, 8, c0, h, c);

    // Layers 2..4 (K=512, split-K 4, 4 chunks each; 128 CTAs)
    const float* Ws[3] = {W2, W3, W4};
    const float* Us[3] = {U2, U3, U4};
    const float* bs[3] = {b2, b3, b4};
    for (int l = 0; l < 3; l++) {
        gemm_bf3<1><<<dim3(G4 / 128, Bn / 128, 4), 256, SMEM_TOTAL>>>(
            hh, hl, Hn, Ws[l], Us[l], G4, zp, G4, Hn / (BK * 4));
        const bool last = (l == 2) && has_tail;
        gates_kernel<<<(Bn * Hn + 255) / 256, 256>>>(zp, bs[l], 4, c,
                                                     last ? out_h : h,
                                                     last ? out_c : c);
    }

    // Decoder (N=32000, K=512, 16 chunks; 500 CTAs) + softmax (bias folded)
    gemm_bf3<0><<<dim3(Vn / 128, Bn / 128, 1), 256, SMEM_TOTAL>>>(
        hh, hl, Hn, Wd, nullptr, Vn, out, Vn, Hn / BK);
    smax_max_kernel<<<Bn, 512>>>(out, bd);
    smax_exp_kernel<<<Bn, 512>>>(out, bd);
    smax_scale_kernel<<<Bn, 512>>>(out);
}

// round 11
// speedup vs baseline: 3.7751x; 1.0023x over previous
#include <cuda_runtime.h>
#include <cuda_bf16.h>
#include <mma.h>
#include <math.h>
#include <cstdint>

using namespace nvcuda;

// -------------------------------------------------------------------------
// Problem dims
// -------------------------------------------------------------------------
constexpr int Bn = 256, Sn = 20, En = 512, Hn = 512, Vn = 32000;
constexpr int XW  = Sn * En + 2 * En;  // 11264
constexpr int KC1 = XW + Hn;           // 11776 (x | h0)
constexpr int G4  = 4 * Hn;            // 2048

// SMEM totals per BK variant (see layout constants in kernel)
constexpr int SMEM32 = 3 * (2 * 128 * 40 * 2) + 2 * (2 * 32 * 136 * 2);   // 96256
constexpr int SMEM64 = 3 * (2 * 128 * 72 * 2) + 2 * (2 * 64 * 136 * 2);   // 180224

// -------------------------------------------------------------------------
// Static device scratch
// -------------------------------------------------------------------------
__device__ __align__(16) __nv_bfloat16 g_a1h[Bn * KC1];
__device__ __align__(16) __nv_bfloat16 g_a1l[Bn * KC1];
__device__ __align__(16) __nv_bfloat16 g_hh[Bn * Hn];
__device__ __align__(16) __nv_bfloat16 g_hl[Bn * Hn];
__device__ __align__(16) float g_zp[8 * Bn * G4];   // split-K partials
__device__ __align__(16) float g_h[Bn * Hn];
__device__ __align__(16) float g_c[Bn * Hn];
__device__ float g_rowmax[Bn];
__device__ float g_rowsum[Bn];

// -------------------------------------------------------------------------
// Helpers
// -------------------------------------------------------------------------
__device__ __forceinline__ uint32_t smem_u32(const void* p) {
    uint32_t a;
    asm("{ .reg .u64 t; cvta.to.shared.u64 t, %1; cvt.u32.u64 %0, t; }" : "=r"(a) : "l"(p));
    return a;
}
__device__ __forceinline__ void cp16(uint32_t s, const void* g) {
    asm volatile("cp.async.cg.shared.global [%0], [%1], 16;" :: "r"(s), "l"(g));
}
#define CP_COMMIT() asm volatile("cp.async.commit_group;" ::: "memory")
#define CP_WAIT1()  asm volatile("cp.async.wait_group 1;" ::: "memory")

__device__ __forceinline__ uint32_t pack_bf2f(float a, float b) {
    __nv_bfloat162 t = __floats2bfloat162_rn(a, b);
    return *reinterpret_cast<uint32_t*>(&t);
}

// -------------------------------------------------------------------------
// GEMM: C[M,N] = A @ B; A = (Ah+Al) bf16 row-major; B fp32 [K][N].
// 3-term split-bf16: hi*hi + hi*lo + lo*hi, with TRUNCATION split for B:
//   bhi = bits&0xFFFF0000 (exact), blo = b - bhi (exact fp32), then blo->bf16.
// 256 threads, 8 warps of 32x64. BKT in {32,64} (templated).
// BMODE: 0 = B1; 1 = B1+B2 elementwise; 2 = rows<XW from B1 else B2.
// split-K via blockIdx.z into partial buffers.
// -------------------------------------------------------------------------
template<int BMODE, int BKT>
__global__ void __launch_bounds__(256, 2)
gemm_bf3(const __nv_bfloat16* __restrict__ Ah, const __nv_bfloat16* __restrict__ Al,
         int lda,
         const float* __restrict__ B1, const float* __restrict__ B2, int ldb,
         float* __restrict__ C, int ldc, int chunks)
{
    // layout constants
    constexpr int A_PITCH = BKT + 8;               // elems
    constexpr int A_ARR   = 128 * A_PITCH * 2;     // bytes
    constexpr int A_SLOT  = 2 * A_ARR;
    constexpr int OFF_B   = 3 * A_SLOT;
    constexpr int B_PITCH = 136;                   // elems (128 + 8 pad)
    constexpr int B_ARR   = BKT * B_PITCH * 2;     // bytes
    constexpr int B_BUF   = 2 * B_ARR;
    constexpr int GPR     = BKT / 8;               // 16B granules per A row
    constexpr int NA      = 128 * GPR / 256;       // A cp iters per array
    constexpr int NB      = BKT / 8;               // float4 per thread for B

    extern __shared__ __align__(16) char smem[];
    const uint32_t sbase = smem_u32(smem);

    const int tid = threadIdx.x;
    const int wid = tid >> 5;
    const int m0 = blockIdx.y * 128;
    const int n0 = blockIdx.x * 128;
    const int kbase = blockIdx.z * chunks * BKT;
    C += (size_t)blockIdx.z * (size_t)(gridDim.y * 128) * ldc;

    const int b_r = tid >> 5;            // B row base (+i*8)
    const int b_c = (tid & 31) << 2;     // B col in elems

    auto issueA = [&](int c, int slot) {
        const int k0 = kbase + c * BKT;
        #pragma unroll
        for (int i = 0; i < NA; i++) {
            const int t2 = tid + i * 256;
            const int row = t2 / GPR;
            const int g   = t2 % GPR;
            const size_t goff = (size_t)(m0 + row) * lda + k0 + g * 8;
            const uint32_t soff = sbase + slot * A_SLOT + row * (A_PITCH * 2) + g * 16;
            cp16(soff,         Ah + goff);
            cp16(soff + A_ARR, Al + goff);
        }
    };

    float4 rB[NB], rB2[NB];
    auto loadB = [&](int c) {
        const int k0 = kbase + c * BKT;
        const float* bp;
        if (BMODE == 2)
            bp = (k0 < XW) ? (B1 + (size_t)k0 * ldb) : (B2 + (size_t)(k0 - XW) * ldb);
        else
            bp = B1 + (size_t)k0 * ldb;
        #pragma unroll
        for (int i = 0; i < NB; i++) {
            const size_t off = (size_t)(b_r + i * 8) * ldb + n0 + b_c;
            rB[i] = *reinterpret_cast<const float4*>(bp + off);
            if (BMODE == 1)
                rB2[i] = *reinterpret_cast<const float4*>(B2 + (size_t)(k0 + b_r + i * 8) * ldb + n0 + b_c);
        }
    };
    auto storeB = [&](int buf) {
        char* bb = smem + OFF_B + buf * B_BUF;
        #pragma unroll
        for (int i = 0; i < NB; i++) {
            float x0 = rB[i].x, x1 = rB[i].y, x2 = rB[i].z, x3 = rB[i].w;
            if (BMODE == 1) { x0 += rB2[i].x; x1 += rB2[i].y; x2 += rB2[i].z; x3 += rB2[i].w; }
            const uint32_t u0 = __float_as_uint(x0), u1 = __float_as_uint(x1);
            const uint32_t u2 = __float_as_uint(x2), u3 = __float_as_uint(x3);
            uint2 hv;
            hv.x = __byte_perm(u0, u1, 0x7632);     // [bf16(x0)|bf16(x1)] (trunc)
            hv.y = __byte_perm(u2, u3, 0x7632);
            const float l0 = x0 - __uint_as_float(u0 & 0xFFFF0000u);
            const float l1 = x1 - __uint_as_float(u1 & 0xFFFF0000u);
            const float l2 = x2 - __uint_as_float(u2 & 0xFFFF0000u);
            const float l3 = x3 - __uint_as_float(u3 & 0xFFFF0000u);
            uint2 lv;
            lv.x = pack_bf2f(l0, l1);
            lv.y = pack_bf2f(l2, l3);
            const int off = (b_r + i * 8) * (B_PITCH * 2) + b_c * 2;   // bytes
            *reinterpret_cast<uint2*>(bb + off)         = hv;
            *reinterpret_cast<uint2*>(bb + B_ARR + off) = lv;
        }
    };

    // warp tile 32x64: warps 4 (M) x 2 (N)
    wmma::fragment<wmma::accumulator, 16, 16, 16, float> acc[2][4];
    #pragma unroll
    for (int i = 0; i < 2; i++)
        #pragma unroll
        for (int j = 0; j < 4; j++)
            wmma::fill_fragment(acc[i][j], 0.0f);

    const int wm = (wid & 3) * 32;
    const int wn = (wid >> 2) * 64;

    // Prologue
    issueA(0, 0); CP_COMMIT();
    if (chunks > 1) issueA(1, 1);
    CP_COMMIT();
    loadB(0);
    storeB(0);

    for (int c = 0; c < chunks; c++) {
        CP_WAIT1();            // A(c) landed (A(c+1) may be in flight)
        __syncthreads();

        if (c + 2 < chunks) issueA(c + 2, (c + 2) % 3);
        CP_COMMIT();
        if (c + 1 < chunks) loadB(c + 1);

        const __nv_bfloat16* sAh = (const __nv_bfloat16*)(smem + (c % 3) * A_SLOT);
        const __nv_bfloat16* sAl = (const __nv_bfloat16*)(smem + (c % 3) * A_SLOT + A_ARR);
        const __nv_bfloat16* sBh = (const __nv_bfloat16*)(smem + OFF_B + (c & 1) * B_BUF);
        const __nv_bfloat16* sBl = (const __nv_bfloat16*)(smem + OFF_B + (c & 1) * B_BUF + B_ARR);
        #pragma unroll
        for (int kk = 0; kk < BKT / 16; kk++) {
            wmma::fragment<wmma::matrix_a, 16, 16, 16, __nv_bfloat16, wmma::row_major> fah[2], fal[2];
            #pragma unroll
            for (int i = 0; i < 2; i++) {
                wmma::load_matrix_sync(fah[i], sAh + (wm + i * 16) * A_PITCH + kk * 16, A_PITCH);
                wmma::load_matrix_sync(fal[i], sAl + (wm + i * 16) * A_PITCH + kk * 16, A_PITCH);
            }
            #pragma unroll
            for (int j = 0; j < 4; j++) {
                wmma::fragment<wmma::matrix_b, 16, 16, 16, __nv_bfloat16, wmma::row_major> fbh, fbl;
                wmma::load_matrix_sync(fbh, sBh + (kk * 16) * B_PITCH + wn + j * 16, B_PITCH);
                wmma::load_matrix_sync(fbl, sBl + (kk * 16) * B_PITCH + wn + j * 16, B_PITCH);
                #pragma unroll
                for (int i = 0; i < 2; i++)
                    wmma::mma_sync(acc[i][j], fah[i], fbh, acc[i][j]);
                #pragma unroll
                for (int i = 0; i < 2; i++)
                    wmma::mma_sync(acc[i][j], fah[i], fbl, acc[i][j]);
                #pragma unroll
                for (int i = 0; i < 2; i++)
                    wmma::mma_sync(acc[i][j], fal[i], fbh, acc[i][j]);
            }
        }

        if (c + 1 < chunks) storeB((c + 1) & 1);
    }

    // Epilogue: direct stores (bias folded downstream)
    #pragma unroll
    for (int i = 0; i < 2; i++)
        #pragma unroll
        for (int j = 0; j < 4; j++) {
            float* cp = C + (size_t)(m0 + wm + i * 16) * ldc + n0 + wn + j * 16;
            wmma::store_matrix_sync(cp, acc[i][j], ldc, wmma::mem_row_major);
        }
}

// -------------------------------------------------------------------------
// Build split-bf16 A for layer 1 (truncation split)
// -------------------------------------------------------------------------
__global__ void build_a1_kernel(const float* __restrict__ enc, const float* __restrict__ word,
                                const float* __restrict__ persona, const int* __restrict__ speaker,
                                const float* __restrict__ h0)
{
    int idx = blockIdx.x * blockDim.x + threadIdx.x;
    if (idx >= Bn * KC1) return;
    int b = idx / KC1, k = idx - b * KC1;
    float v;
    if (k < Sn * En)           v = enc[(size_t)b * Sn * En + k];
    else if (k < Sn * En + En) v = word[b * En + k - Sn * En];
    else if (k < XW)           v = persona[(size_t)speaker[b] * En + k - (Sn * En + En)];
    else                       v = h0[b * Hn + k - XW];
    const uint32_t u = __float_as_uint(v);
    reinterpret_cast<uint16_t*>(g_a1h)[idx] = (uint16_t)(u >> 16);
    const float lo = v - __uint_as_float(u & 0xFFFF0000u);
    g_a1l[idx] = __float2bfloat16(lo);
}

// -------------------------------------------------------------------------
// Gates: reduce split-K partials + bias, LSTM cell, emit h (fp32 + hi/lo)
// -------------------------------------------------------------------------
__device__ __forceinline__ float sigf(float x) { return 1.0f / (1.0f + __expf(-x)); }

__global__ void gates_kernel(const float* __restrict__ zp, const float* __restrict__ bias,
                             int nsplit, const float* __restrict__ c_in,
                             float* __restrict__ h_out, float* __restrict__ c_out)
{
    int idx = blockIdx.x * blockDim.x + threadIdx.x;
    if (idx >= Bn * Hn) return;
    int b = idx >> 9, j = idx & (Hn - 1);
    float zg[4];
    #pragma unroll
    for (int g = 0; g < 4; g++) {
        float s = bias[g * Hn + j];
        for (int sp = 0; sp < nsplit; sp++)
            s += zp[(size_t)sp * Bn * G4 + (size_t)b * G4 + g * Hn + j];
        zg[g] = s;
    }
    float gi = sigf(zg[0]);
    float gf = sigf(zg[1]);
    float gg = fmaxf(zg[2], 0.f);
    float go = sigf(zg[3]);
    float c = gf * c_in[idx] + gi * gg;
    c_out[idx] = c;
    float h = go * fmaxf(c, 0.f);
    h_out[idx] = h;
    const uint32_t u = __float_as_uint(h);
    reinterpret_cast<uint16_t*>(g_hh)[idx] = (uint16_t)(u >> 16);
    g_hl[idx] = __float2bfloat16(h - __uint_as_float(u & 0xFFFF0000u));
}

// -------------------------------------------------------------------------
// Softmax, 3 passes, exp computed once, decoder bias folded in.
// -------------------------------------------------------------------------
__global__ void smax_max_kernel(const float* __restrict__ logits, const float* __restrict__ bd)
{
    __shared__ float red[16];
    const int b = blockIdx.x;
    const float* row = logits + (size_t)b * Vn;
    const int tid = threadIdx.x;
    float m = -1e30f;
    for (int j = tid; j < Vn; j += 512) m = fmaxf(m, row[j] + bd[j]);
    #pragma unroll
    for (int o = 16; o; o >>= 1) m = fmaxf(m, __shfl_xor_sync(0xffffffffu, m, o));
    if ((tid & 31) == 0) red[tid >> 5] = m;
    __syncthreads();
    if (tid < 32) {
        float mm = (tid < 16) ? red[tid] : -1e30f;
        #pragma unroll
        for (int o = 8; o; o >>= 1) mm = fmaxf(mm, __shfl_xor_sync(0xffffffffu, mm, o));
        if (tid == 0) g_rowmax[b] = mm;
    }
}

__global__ void smax_exp_kernel(float* __restrict__ logits, const float* __restrict__ bd)
{
    __shared__ float red[16];
    const int b = blockIdx.x;
    float* row = logits + (size_t)b * Vn;
    const int tid = threadIdx.x;
    const float m = g_rowmax[b];
    float s = 0.f;
    for (int j = tid; j < Vn; j += 512) {
        float e = __expf(row[j] + bd[j] - m);
        row[j] = e;
        s += e;
    }
    #pragma unroll
    for (int o = 16; o; o >>= 1) s += __shfl_xor_sync(0xffffffffu, s, o);
    if ((tid & 31) == 0) red[tid >> 5] = s;
    __syncthreads();
    if (tid < 32) {
        float ss = (tid < 16) ? red[tid] : 0.f;
        #pragma unroll
        for (int o = 8; o; o >>= 1) ss += __shfl_xor_sync(0xffffffffu, ss, o);
        if (tid == 0) g_rowsum[b] = ss;
    }
}

__global__ void smax_scale_kernel(float* __restrict__ logits)
{
    const int b = blockIdx.x;
    float* row = logits + (size_t)b * Vn;
    const float inv = 1.0f / g_rowsum[b];
    for (int j = threadIdx.x; j < Vn; j += 512) row[j] *= inv;
}

// -------------------------------------------------------------------------
// Launch
// -------------------------------------------------------------------------
extern "C" void kernel_launch(void* const* d_in, const int* in_sizes, int n_in,
                              void* d_out, int out_size)
{
    const float* enc     = (const float*)d_in[0];
    const float* word    = (const float*)d_in[1];
    const float* h0      = (const float*)d_in[2];
    const float* c0      = (const float*)d_in[3];
    const int*   speaker = (const int*)  d_in[4];
    const float* persona = (const float*)d_in[6];
    const float* W1 = (const float*)d_in[7];
    const float* U1 = (const float*)d_in[8];
    const float* b1 = (const float*)d_in[9];
    const float* W2 = (const float*)d_in[10];
    const float* U2 = (const float*)d_in[11];
    const float* b2 = (const float*)d_in[12];
    const float* W3 = (const float*)d_in[13];
    const float* U3 = (const float*)d_in[14];
    const float* b3 = (const float*)d_in[15];
    const float* W4 = (const float*)d_in[16];
    const float* U4 = (const float*)d_in[17];
    const float* b4 = (const float*)d_in[18];
    const float* Wd = (const float*)d_in[19];
    const float* bd = (const float*)d_in[20];
    float* out = (float*)d_out;

    static bool attr_done = false;
    if (!attr_done) {
        cudaFuncSetAttribute(gemm_bf3<2, 32>, cudaFuncAttributeMaxDynamicSharedMemorySize, SMEM32);
        cudaFuncSetAttribute(gemm_bf3<0, 32>, cudaFuncAttributeMaxDynamicSharedMemorySize, SMEM32);
        cudaFuncSetAttribute(gemm_bf3<1, 64>, cudaFuncAttributeMaxDynamicSharedMemorySize, SMEM64);
        attr_done = true;
    }

    void *p_a1h, *p_a1l, *p_hh, *p_hl, *p_zp, *p_h, *p_c;
    cudaGetSymbolAddress(&p_a1h, g_a1h);
    cudaGetSymbolAddress(&p_a1l, g_a1l);
    cudaGetSymbolAddress(&p_hh,  g_hh);
    cudaGetSymbolAddress(&p_hl,  g_hl);
    cudaGetSymbolAddress(&p_zp,  g_zp);
    cudaGetSymbolAddress(&p_h,   g_h);
    cudaGetSymbolAddress(&p_c,   g_c);
    __nv_bfloat16* a1h = (__nv_bfloat16*)p_a1h;
    __nv_bfloat16* a1l = (__nv_bfloat16*)p_a1l;
    __nv_bfloat16* hh  = (__nv_bfloat16*)p_hh;
    __nv_bfloat16* hl  = (__nv_bfloat16*)p_hl;
    float* zp = (float*)p_zp;
    float* h  = (float*)p_h;
    float* c  = (float*)p_c;

    float* out_h = out + (size_t)Bn * Vn;
    float* out_c = out_h + (size_t)Bn * Hn;
    const bool has_tail = (out_size >= Bn * Vn + 2 * Bn * Hn);

    // Layer 1 (K=11776, BK32, split-K 8, 46 chunks; 256 CTAs, 2/SM)
    build_a1_kernel<<<(Bn * KC1 + 255) / 256, 256>>>(enc, word, persona, speaker, h0);
    gemm_bf3<2, 32><<<dim3(G4 / 128, Bn / 128, 8), 256, SMEM32>>>(
        a1h, a1l, KC1, W1, U1, G4, zp, G4, KC1 / (32 * 8));
    gates_kernel<<<(Bn * Hn + 255) / 256, 256>>>(zp, b1, 8, c0, h, c);

    // Layers 2..4 (K=512, BK64, split-K 4, 2 chunks; 128 CTAs, 1/SM)
    const float* Ws[3] = {W2, W3, W4};
    const float* Us[3] = {U2, U3, U4};
    const float* bs[3] = {b2, b3, b4};
    for (int l = 0; l < 3; l++) {
        gemm_bf3<1, 64><<<dim3(G4 / 128, Bn / 128, 4), 256, SMEM64>>>(
            hh, hl, Hn, Ws[l], Us[l], G4, zp, G4, Hn / (64 * 4));
        const bool last = (l == 2) && has_tail;
        gates_kernel<<<(Bn * Hn + 255) / 256, 256>>>(zp, bs[l], 4, c,
                                                     last ? out_h : h,
                                                     last ? out_c : c);
    }

    // Decoder (N=32000, K=512, BK32, 16 chunks; 500 CTAs, 2/SM) + softmax
    gemm_bf3<0, 32><<<dim3(Vn / 128, Bn / 128, 1), 256, SMEM32>>>(
        hh, hl, Hn, Wd, nullptr, Vn, out, Vn, Hn / 32);
    smax_max_kernel<<<Bn, 512>>>(out, bd);
    smax_exp_kernel<<<Bn, 512>>>(out, bd);
    smax_scale_kernel<<<Bn, 512>>>(out);
}